// round 2
// baseline (speedup 1.0000x reference)
#include <cuda_runtime.h>
#include <math.h>

// Problem constants
#define B_   256
#define T_   128
#define I_   512
#define H_   512
#define NN   1024
#define MM   512
#define OO   512
#define PSTR 520        // padded row stride for P buffers (M+6=518 -> 520)
#define EPS  1e-8f
#define NB   132        // persistent blocks (<= 148 SMs -> all co-resident)

// ---------------- persistent device state (no allocs allowed) ----------------
__device__ __align__(256) float g_mem[NN * MM];
__device__ __align__(256) float g_wr[B_ * NN];
__device__ __align__(256) float g_ww[B_ * NN];
__device__ __align__(256) float g_EA[B_ * 2 * MM];   // e=sigmoid cols[0,M), a=tanh cols[M,2M)
__device__ __align__(256) float g_r0[B_ * MM];       // split-K partials of r = wr @ mem
__device__ __align__(256) float g_r1[B_ * MM];
__device__ __align__(256) float g_hx[B_ * H_];       // x@Wx partial (pre-activation)
__device__ __align__(256) float g_hr[B_ * H_];       // r@Wr partial; h = tanh(hx+hr+bh)
__device__ __align__(256) float g_Pw[B_ * PSTR];
__device__ __align__(256) float g_Pr[B_ * PSTR];
__device__ __align__(256) float g_Cw[B_ * NN];
__device__ __align__(256) float g_Cr[B_ * NN];
__device__ __align__(256) float g_memnorm[NN];
__device__ unsigned g_cnt;
__device__ volatile unsigned g_sense;

// ---------------- helpers ----------------
__device__ __forceinline__ float sigmoidf_(float x) { return 1.f / (1.f + expf(-x)); }
__device__ __forceinline__ float softplusf_(float x) {
    return fmaxf(x, 0.f) + log1pf(expf(-fabsf(x)));
}
__device__ __forceinline__ float warpSum(float v) {
    #pragma unroll
    for (int o = 16; o; o >>= 1) v += __shfl_xor_sync(0xffffffffu, v, o);
    return v;
}
__device__ __forceinline__ float warpMax(float v) {
    #pragma unroll
    for (int o = 16; o; o >>= 1) v = fmaxf(v, __shfl_xor_sync(0xffffffffu, v, o));
    return v;
}
__device__ float blockSum(float v, float* red) {
    int lane = threadIdx.x & 31, w = threadIdx.x >> 5;
    v = warpSum(v);
    if (lane == 0) red[w] = v;
    __syncthreads();
    if (threadIdx.x == 0) {
        float s = 0.f;
        for (int i = 0; i < 8; i++) s += red[i];
        red[32] = s;
    }
    __syncthreads();
    float r = red[32];
    __syncthreads();
    return r;
}
__device__ float blockMax(float v, float* red) {
    int lane = threadIdx.x & 31, w = threadIdx.x >> 5;
    v = warpMax(v);
    if (lane == 0) red[w] = v;
    __syncthreads();
    if (threadIdx.x == 0) {
        float m = red[0];
        for (int i = 1; i < 8; i++) m = fmaxf(m, red[i]);
        red[32] = m;
    }
    __syncthreads();
    float r = red[32];
    __syncthreads();
    return r;
}

// ---------------- software grid barrier (sense reversal) ----------------
// Total barriers per kernel run MUST be even so g_sense returns to 0.
__device__ __forceinline__ void gbar(unsigned& sense) {
    __threadfence();                      // release all this block's writes
    __syncthreads();
    if (threadIdx.x == 0) {
        unsigned ns = sense ^ 1u;
        if (atomicAdd(&g_cnt, 1u) == NB - 1u) {
            atomicExch(&g_cnt, 0u);
            __threadfence();
            g_sense = ns;
        } else {
            while (g_sense != ns) __nanosleep(64);
        }
        sense = ns;
        __threadfence();                  // acquire (gpu-scope fence invalidates L1D)
    }
    __syncthreads();
}

// ---------------- generic 64x64 GEMM tile ----------------
// C[row0:+64, col0:+64] = act(Acomb @ W + bias)
// AMODE: 0 plain A, 1 A+A2, 2 tanh(A+A2+Abias[k])   (Abias indexed by k-column)
// ACT:   0 none, 2 sigmoid, 3 tanh iff col<MM, 4 sigmoid iff col<MM else tanh
// WG4:   W loads via float4 (needs wcols%4==0 and full tile)
template <int ACT, int AMODE, bool WG4>
__device__ __forceinline__ void gemm_tile(
    float* sh,
    const float* __restrict__ A, const float* __restrict__ A2,
    const float* __restrict__ Abias, size_t lda,
    const float* __restrict__ W, int wcols,
    const float* __restrict__ bias,
    float* __restrict__ C, size_t ldc,
    int K, int row0, int col0)
{
    float* shA = sh;
    float* shB = sh + 1024;
    const int tid = threadIdx.x;
    const int tx = tid & 15, ty = tid >> 4;
    float acc[4][4] = {};
    const int aR = tid >> 2, aK4 = (tid & 3) * 4;

    for (int k0 = 0; k0 < K; k0 += 16) {
        size_t abase = (size_t)(row0 + aR) * lda + k0 + aK4;
        float4 av = *(const float4*)(A + abase);
        if (AMODE >= 1) {
            float4 a2 = *(const float4*)(A2 + abase);
            av.x += a2.x; av.y += a2.y; av.z += a2.z; av.w += a2.w;
        }
        if (AMODE == 2) {
            av.x = tanhf(av.x + Abias[k0 + aK4 + 0]);
            av.y = tanhf(av.y + Abias[k0 + aK4 + 1]);
            av.z = tanhf(av.z + Abias[k0 + aK4 + 2]);
            av.w = tanhf(av.w + Abias[k0 + aK4 + 3]);
        }
        shA[(aK4 + 0) * 64 + aR] = av.x;
        shA[(aK4 + 1) * 64 + aR] = av.y;
        shA[(aK4 + 2) * 64 + aR] = av.z;
        shA[(aK4 + 3) * 64 + aR] = av.w;
        if (WG4) {
            int bK = tid >> 4, bC = (tid & 15) * 4;
            *(float4*)&shB[bK * 64 + bC] =
                *(const float4*)(W + (size_t)(k0 + bK) * wcols + col0 + bC);
        } else {
            int bK = tid >> 4, bC = tid & 15;
            #pragma unroll
            for (int u = 0; u < 4; u++) {
                int c = col0 + bC + u * 16;
                shB[bK * 64 + bC + u * 16] =
                    (c < wcols) ? W[(size_t)(k0 + bK) * wcols + c] : 0.f;
            }
        }
        __syncthreads();
        #pragma unroll
        for (int k = 0; k < 16; k++) {
            float4 a4 = *(const float4*)&shA[k * 64 + ty * 4];
            float4 b4 = *(const float4*)&shB[k * 64 + tx * 4];
            float a[4] = {a4.x, a4.y, a4.z, a4.w};
            float b[4] = {b4.x, b4.y, b4.z, b4.w};
            #pragma unroll
            for (int i = 0; i < 4; i++)
                #pragma unroll
                for (int j = 0; j < 4; j++)
                    acc[i][j] = fmaf(a[i], b[j], acc[i][j]);
        }
        __syncthreads();
    }

    int rb = row0 + ty * 4, cb = col0 + tx * 4;
    #pragma unroll
    for (int j = 0; j < 4; j++) {
        int c = cb + j;
        if (c < wcols) {
            float bv = bias ? bias[c] : 0.f;
            #pragma unroll
            for (int i = 0; i < 4; i++) {
                float v = acc[i][j] + bv;
                if (ACT == 2) v = sigmoidf_(v);
                else if (ACT == 3) { if (c < MM) v = tanhf(v); }
                else if (ACT == 4) { v = (c < MM) ? sigmoidf_(v) : tanhf(v); }
                C[(size_t)(rb + i) * ldc + c] = v;
            }
        }
    }
}

// ---------------- memory update tile: mem = mem*(1 - ww^T e/B) + ww^T a/B ----
__device__ __forceinline__ void memupd_tile(float* sh, int m0, int n0) {
    float* Ws = sh;
    float* Es = sh + 1024;
    float* Aa = sh + 2048;
    const int tid = threadIdx.x;
    const int tx = tid & 15, ty = tid >> 4;
    float ae[4][4] = {}, aa[4][4] = {};
    const int lK = tid >> 4, lC = (tid & 15) * 4;

    for (int b0 = 0; b0 < B_; b0 += 16) {
        *(float4*)&Ws[lK * 64 + lC] = *(const float4*)(g_ww + (size_t)(b0 + lK) * NN + n0 + lC);
        *(float4*)&Es[lK * 64 + lC] = *(const float4*)(g_EA + (size_t)(b0 + lK) * (2 * MM) + m0 + lC);
        *(float4*)&Aa[lK * 64 + lC] = *(const float4*)(g_EA + (size_t)(b0 + lK) * (2 * MM) + MM + m0 + lC);
        __syncthreads();
        #pragma unroll
        for (int k = 0; k < 16; k++) {
            float4 w4 = *(const float4*)&Ws[k * 64 + ty * 4];
            float4 e4 = *(const float4*)&Es[k * 64 + tx * 4];
            float4 a4 = *(const float4*)&Aa[k * 64 + tx * 4];
            float w[4] = {w4.x, w4.y, w4.z, w4.w};
            float e[4] = {e4.x, e4.y, e4.z, e4.w};
            float a[4] = {a4.x, a4.y, a4.z, a4.w};
            #pragma unroll
            for (int i = 0; i < 4; i++)
                #pragma unroll
                for (int j = 0; j < 4; j++) {
                    ae[i][j] = fmaf(w[i], e[j], ae[i][j]);
                    aa[i][j] = fmaf(w[i], a[j], aa[i][j]);
                }
        }
        __syncthreads();
    }
    const float invB = 1.f / (float)B_;
    #pragma unroll
    for (int i = 0; i < 4; i++)
        #pragma unroll
        for (int j = 0; j < 4; j++) {
            size_t idx = (size_t)(n0 + ty * 4 + i) * MM + m0 + tx * 4 + j;
            float mo = g_mem[idx];
            g_mem[idx] = mo * (1.f - ae[i][j] * invB) + aa[i][j] * invB;
        }
}

// ---------------- scores tile: C[b][n] = key[b,:] . mem[n,:] ----------------
__device__ __forceinline__ void scores_tile(float* sh, const float* __restrict__ Key,
                                            float* __restrict__ Cout, int b0, int n0) {
    float* Ks = sh;
    float* Ms = sh + 1024;
    const int tid = threadIdx.x;
    const int tx = tid & 15, ty = tid >> 4;
    float acc[4][4] = {};
    const int lR = tid >> 2, lK4 = (tid & 3) * 4;

    for (int m0 = 0; m0 < MM; m0 += 16) {
        float4 kv = *(const float4*)(Key + (size_t)(b0 + lR) * PSTR + m0 + lK4);
        Ks[(lK4 + 0) * 64 + lR] = kv.x;
        Ks[(lK4 + 1) * 64 + lR] = kv.y;
        Ks[(lK4 + 2) * 64 + lR] = kv.z;
        Ks[(lK4 + 3) * 64 + lR] = kv.w;
        float4 mv = *(const float4*)(g_mem + (size_t)(n0 + lR) * MM + m0 + lK4);
        Ms[(lK4 + 0) * 64 + lR] = mv.x;
        Ms[(lK4 + 1) * 64 + lR] = mv.y;
        Ms[(lK4 + 2) * 64 + lR] = mv.z;
        Ms[(lK4 + 3) * 64 + lR] = mv.w;
        __syncthreads();
        #pragma unroll
        for (int k = 0; k < 16; k++) {
            float4 a4 = *(const float4*)&Ks[k * 64 + ty * 4];
            float4 b4 = *(const float4*)&Ms[k * 64 + tx * 4];
            float a[4] = {a4.x, a4.y, a4.z, a4.w};
            float b[4] = {b4.x, b4.y, b4.z, b4.w};
            #pragma unroll
            for (int i = 0; i < 4; i++)
                #pragma unroll
                for (int j = 0; j < 4; j++)
                    acc[i][j] = fmaf(a[i], b[j], acc[i][j]);
        }
        __syncthreads();
    }
    #pragma unroll
    for (int i = 0; i < 4; i++)
        #pragma unroll
        for (int j = 0; j < 4; j++)
            Cout[(size_t)(b0 + ty * 4 + i) * NN + n0 + tx * 4 + j] = acc[i][j];
}

// ---------------- per-row memory norms (32 rows per job) ----------------
__device__ __forceinline__ void norm_job(int nj) {
    const int t = threadIdx.x;
    const int row = nj * 32 + (t >> 3);
    const int p = t & 7;
    const float* rp = g_mem + (size_t)row * MM;
    float s = 0.f;
    #pragma unroll
    for (int u = 0; u < 64; u++) {
        float v = rp[p + u * 8];
        s += v * v;
    }
    s += __shfl_xor_sync(0xffffffffu, s, 1);
    s += __shfl_xor_sync(0xffffffffu, s, 2);
    s += __shfl_xor_sync(0xffffffffu, s, 4);
    if (p == 0) g_memnorm[row] = sqrtf(s);
}

// ---------------- addressing: softmax -> interp -> shift -> sharpen ---------
__device__ void addr_job(float* sh, int b, int z) {
    float* swg  = sh;           // [0,1024)
    float* red  = sh + 1024;    // [1024,1057)
    float* scal = sh + 1060;    // [1060,1067)
    const float* P = (z ? g_Pr : g_Pw) + (size_t)b * PSTR;
    const float* C = (z ? g_Cr : g_Cw) + (size_t)b * NN;
    float* wrow = (z ? g_wr : g_ww) + (size_t)b * NN;
    const int tid = threadIdx.x;

    float s = 0.f;
    for (int i = tid; i < MM; i += 256) {
        float k = P[i];
        s += k * k;
    }
    s = blockSum(s, red);
    if (tid == 0) {
        scal[6] = sqrtf(s) + EPS;
        float p0 = P[MM], p1 = P[MM + 1], p2 = P[MM + 2];
        float p3 = P[MM + 3], p4 = P[MM + 4], p5 = P[MM + 5];
        scal[0] = softplusf_(p0);
        scal[1] = sigmoidf_(p1);
        float m = fmaxf(p2, fmaxf(p3, p4));
        float e0 = expf(p2 - m), e1 = expf(p3 - m), e2 = expf(p4 - m);
        float ss = e0 + e1 + e2;
        scal[2] = e0 / ss; scal[3] = e1 / ss; scal[4] = e2 / ss;
        scal[5] = 1.f + softplusf_(p5);
    }
    __syncthreads();
    float beta = scal[0], gg = scal[1], s0 = scal[2], s1 = scal[3], s2 = scal[4];
    float gamma = scal[5], knorm = scal[6];

    float v[4];
    float mx = -3.4e38f;
    #pragma unroll
    for (int u = 0; u < 4; u++) {
        int n = tid + u * 256;
        float sc = beta * C[n] / (knorm * (g_memnorm[n] + EPS));
        v[u] = sc;
        mx = fmaxf(mx, sc);
    }
    mx = blockMax(mx, red);
    float se = 0.f;
    #pragma unroll
    for (int u = 0; u < 4; u++) {
        v[u] = expf(v[u] - mx);
        se += v[u];
    }
    se = blockSum(se, red);
    float inv = 1.f / se;
    #pragma unroll
    for (int u = 0; u < 4; u++) {
        int n = tid + u * 256;
        float wc = v[u] * inv;
        swg[n] = gg * wc + (1.f - gg) * wrow[n];
    }
    __syncthreads();
    float S = 0.f;
    #pragma unroll
    for (int u = 0; u < 4; u++) {
        int n = tid + u * 256;
        float wt = s1 * swg[n] + s0 * swg[(n + 1) & (NN - 1)] + s2 * swg[(n - 1) & (NN - 1)];
        v[u] = powf(wt, gamma);
        S += v[u];
    }
    S = blockSum(S, red);
    float invS = 1.f / (S + EPS);
    #pragma unroll
    for (int u = 0; u < 4; u++)
        wrow[tid + u * 256] = v[u] * invS;
    __syncthreads();
}

// ---------------- the megakernel ----------------
__global__ void __launch_bounds__(256) ntm_mega(
    const float* __restrict__ x,
    const float* __restrict__ mem0, const float* __restrict__ wr0,
    const float* __restrict__ ww0, const float* __restrict__ h0,
    const float* __restrict__ Wx, const float* __restrict__ Wr,
    const float* __restrict__ bh,
    const float* __restrict__ Whr, const float* __restrict__ bhr,
    const float* __restrict__ Whw, const float* __restrict__ bhw,
    const float* __restrict__ Wea, const float* __restrict__ bea,
    const float* __restrict__ Wo, const float* __restrict__ bo,
    float* __restrict__ out)
{
    __shared__ float sh[3 * 1024 + 80];
    unsigned sense = 0;
    const int bid = blockIdx.x;
    const int tid = threadIdx.x;
    const int gthread = bid * 256 + tid;

    // Phase 0: init state from inputs (in-kernel; no memcpy graph nodes)
    for (int i = gthread; i < NN * MM; i += NB * 256) g_mem[i] = mem0[i];
    for (int i = gthread; i < B_ * NN; i += NB * 256) {
        g_wr[i] = wr0[i];
        g_ww[i] = ww0[i];
    }
    gbar(sense);                                           // barrier 1

    // Initial EA from h0 (plain A; h0 is post-activation carry)
    for (int j = bid; j < 64; j += NB) {
        int row0 = (j & 3) * 64, col0 = (j >> 2) * 64;
        gemm_tile<4, 0, true>(sh, h0, nullptr, nullptr, H_,
                              Wea, 2 * MM, bea, g_EA, 2 * MM, H_, row0, col0);
    }
    gbar(sense);                                           // barrier 2

    for (int t = 0; t < T_; t++) {
        // P1: memory erase/add (uses carry ww + EA from carry h)
        for (int j = bid; j < 128; j += NB)
            memupd_tile(sh, (j & 7) * 64, (j >> 3) * 64);
        gbar(sense);

        // P2: r = wr @ mem (split-K partials) + per-row mem norms
        for (int j = bid; j < 96; j += NB) {
            if (j < 32) {
                int row0 = (j & 3) * 64, col0 = (j >> 2) * 64;
                gemm_tile<0, 0, true>(sh, g_wr, nullptr, nullptr, NN,
                                      g_mem, MM, nullptr, g_r0, MM, 512, row0, col0);
            } else if (j < 64) {
                int jj = j - 32;
                int row0 = (jj & 3) * 64, col0 = (jj >> 2) * 64;
                gemm_tile<0, 0, true>(sh, g_wr + 512, nullptr, nullptr, NN,
                                      g_mem + (size_t)512 * MM, MM, nullptr,
                                      g_r1, MM, 512, row0, col0);
            } else {
                norm_job(j - 64);
            }
        }
        gbar(sense);

        // P3: h partials (hx = x_t@Wx, hr = (r0+r1)@Wr); h = tanh(hx+hr+bh) fused later
        for (int j = bid; j < 64; j += NB) {
            if (j < 32) {
                int row0 = (j & 3) * 64, col0 = (j >> 2) * 64;
                gemm_tile<0, 0, true>(sh, x + (size_t)t * I_, nullptr, nullptr,
                                      (size_t)T_ * I_, Wx, H_, nullptr,
                                      g_hx, H_, I_, row0, col0);
            } else {
                int jj = j - 32;
                int row0 = (jj & 3) * 64, col0 = (jj >> 2) * 64;
                gemm_tile<0, 1, true>(sh, g_r0, g_r1, nullptr, MM,
                                      Wr, H_, nullptr, g_hr, H_, MM, row0, col0);
            }
        }
        gbar(sense);

        // P4: Pw(36) + Pr(36) + out(32) + EA-for-next-step(64) — all consume h via fused tanh
        for (int j = bid; j < 168; j += NB) {
            if (j < 36) {
                int row0 = (j % 4) * 64, col0 = (j / 4) * 64;
                gemm_tile<3, 2, false>(sh, g_hx, g_hr, bh, H_,
                                       Whw, MM + 6, bhw, g_Pw, PSTR, H_, row0, col0);
            } else if (j < 72) {
                int jj = j - 36;
                int row0 = (jj % 4) * 64, col0 = (jj / 4) * 64;
                gemm_tile<3, 2, false>(sh, g_hx, g_hr, bh, H_,
                                       Whr, MM + 6, bhr, g_Pr, PSTR, H_, row0, col0);
            } else if (j < 104) {
                int jj = j - 72;
                int row0 = (jj & 3) * 64, col0 = (jj >> 2) * 64;
                gemm_tile<2, 2, true>(sh, g_hx, g_hr, bh, H_,
                                      Wo, OO, bo, out + (size_t)t * OO,
                                      (size_t)T_ * OO, H_, row0, col0);
            } else {
                int jj = j - 104;
                int row0 = (jj & 3) * 64, col0 = (jj >> 2) * 64;
                gemm_tile<4, 2, true>(sh, g_hx, g_hr, bh, H_,
                                      Wea, 2 * MM, bea, g_EA, 2 * MM, H_, row0, col0);
            }
        }
        gbar(sense);

        // P5: content scores for both heads
        for (int j = bid; j < 128; j += NB) {
            int z = j >> 6, jj = j & 63;
            int b0 = (jj & 3) * 64, n0 = (jj >> 2) * 64;
            scores_tile(sh, z ? g_Pr : g_Pw, z ? g_Cr : g_Cw, b0, n0);
        }
        gbar(sense);

        // P6: addressing finalize -> new wr, ww (in place)
        for (int j = bid; j < 512; j += NB)
            addr_job(sh, j & 255, j >> 8);
        gbar(sense);
    }
    // total barriers: 2 + 6*128 = 770 (even) -> g_sense returns to 0 for next run
}

// ---------------- host launcher: ONE kernel node ----------------
extern "C" void kernel_launch(void* const* d_in, const int* in_sizes, int n_in,
                              void* d_out, int out_size)
{
    (void)in_sizes; (void)n_in; (void)out_size;
    ntm_mega<<<NB, 256>>>(
        (const float*)d_in[0],  (const float*)d_in[1],  (const float*)d_in[2],
        (const float*)d_in[3],  (const float*)d_in[4],  (const float*)d_in[5],
        (const float*)d_in[6],  (const float*)d_in[7],  (const float*)d_in[8],
        (const float*)d_in[9],  (const float*)d_in[10], (const float*)d_in[11],
        (const float*)d_in[12], (const float*)d_in[13], (const float*)d_in[14],
        (const float*)d_in[15], (float*)d_out);
}

// round 3
// speedup vs baseline: 1.0925x; 1.0925x over previous
#include <cuda_runtime.h>
#include <math.h>

#define B_   256
#define T_   128
#define I_   512
#define H_   512
#define NN   1024
#define MM   512
#define OO   512
#define PSTR 520
#define EPS  1e-8f
#define NB   132

// ---------------- persistent device state ----------------
__device__ __align__(256) float g_mem[NN * MM];
__device__ __align__(256) float g_wr[B_ * NN];
__device__ __align__(256) float g_ww[B_ * NN];
__device__ __align__(256) float g_EA0[B_ * 2 * MM];   // raw EA partials (K-split)
__device__ __align__(256) float g_EA1[B_ * 2 * MM];
__device__ __align__(256) float g_rp[4][B_ * MM];     // r = wr@mem 4-way K-split partials
__device__ __align__(256) float g_hxp[2][2][B_ * H_]; // [parity][ksplit] x@Wx partials
__device__ __align__(256) float g_hrp[2][B_ * H_];    // r@Wr partials
__device__ __align__(256) float g_Pw0[B_ * PSTR];
__device__ __align__(256) float g_Pw1[B_ * PSTR];
__device__ __align__(256) float g_Pr0[B_ * PSTR];
__device__ __align__(256) float g_Pr1[B_ * PSTR];
__device__ __align__(256) float g_Cw0[B_ * NN];
__device__ __align__(256) float g_Cw1[B_ * NN];
__device__ __align__(256) float g_Cr0[B_ * NN];
__device__ __align__(256) float g_Cr1[B_ * NN];
__device__ __align__(256) float g_op0[B_ * OO];
__device__ __align__(256) float g_op1[B_ * OO];
__device__ __align__(256) float g_memnorm[NN];
__device__ unsigned g_cnt;
__device__ volatile unsigned g_sense;

// ---------------- helpers ----------------
__device__ __forceinline__ float sigmoidf_(float x) { return 1.f / (1.f + expf(-x)); }
__device__ __forceinline__ float softplusf_(float x) {
    return fmaxf(x, 0.f) + log1pf(expf(-fabsf(x)));
}
__device__ __forceinline__ float warpSum(float v) {
    #pragma unroll
    for (int o = 16; o; o >>= 1) v += __shfl_xor_sync(0xffffffffu, v, o);
    return v;
}
__device__ __forceinline__ float warpMax(float v) {
    #pragma unroll
    for (int o = 16; o; o >>= 1) v = fmaxf(v, __shfl_xor_sync(0xffffffffu, v, o));
    return v;
}
__device__ float blockSum(float v, float* red) {
    int lane = threadIdx.x & 31, w = threadIdx.x >> 5;
    v = warpSum(v);
    if (lane == 0) red[w] = v;
    __syncthreads();
    if (threadIdx.x == 0) {
        float s = 0.f;
        for (int i = 0; i < 8; i++) s += red[i];
        red[32] = s;
    }
    __syncthreads();
    float r = red[32];
    __syncthreads();
    return r;
}
__device__ float blockMax(float v, float* red) {
    int lane = threadIdx.x & 31, w = threadIdx.x >> 5;
    v = warpMax(v);
    if (lane == 0) red[w] = v;
    __syncthreads();
    if (threadIdx.x == 0) {
        float m = red[0];
        for (int i = 1; i < 8; i++) m = fmaxf(m, red[i]);
        red[32] = m;
    }
    __syncthreads();
    float r = red[32];
    __syncthreads();
    return r;
}

__device__ __forceinline__ void gbar(unsigned& sense) {
    __threadfence();
    __syncthreads();
    if (threadIdx.x == 0) {
        unsigned ns = sense ^ 1u;
        if (atomicAdd(&g_cnt, 1u) == NB - 1u) {
            atomicExch(&g_cnt, 0u);
            __threadfence();
            g_sense = ns;
        } else {
            while (g_sense != ns) __nanosleep(64);
        }
        sense = ns;
        __threadfence();
    }
    __syncthreads();
}

// ---------------- 128x64 double-buffered GEMM tile, 8x4 per thread ----------
// A (128 x K) built from up to 4 summed sources (+optional k-bias, +tanh).
// BMODE 0: W row-major (K x wld) float4; 1: row-major scalar+col guard; 2:
// B[k][n] = Wsrc[n*wld + k] (transposed source, e.g. mem rows as columns).
// All pointers pre-offset: A* -> (row0, kofs); Wsrc -> (kofs, col0) for
// BMODE 0/1 or (n0, kofs) for 2; Cdst -> (row0, col0); abias/cbias offset.
template<int NSRC, bool ATANH, bool ABIAS, int BMODE>
__device__ void tile_gemm(
    float* sh,
    const float* __restrict__ A0, const float* __restrict__ A1,
    const float* __restrict__ A2, const float* __restrict__ A3,
    const float* __restrict__ abias, int lda,
    const float* __restrict__ Wsrc, int wld, int wvalid,
    const float* __restrict__ cbias,
    float* __restrict__ Cdst, int ldc, int K)
{
    float* As = sh;            // [2][16][132]
    float* Bs = sh + 4224;     // [2][16][64]
    const int tid = threadIdx.x;
    const int aR = tid >> 1, aK = (tid & 1) * 8;
    const int bK = tid >> 4, bC = (tid & 15) * 4;
    const int tnN = tid >> 2, tm4 = (tid & 3) * 4;
    const int ty = tid >> 4, tx = tid & 15;

    float ar[8], bw[4];

    auto loadA = [&](int k0) {
        #pragma unroll
        for (int hh = 0; hh < 2; hh++) {
            int kk = k0 + aK + hh * 4;
            float4 v = *(const float4*)(A0 + (size_t)aR * lda + kk);
            if (NSRC > 1) {
                float4 u = *(const float4*)(A1 + (size_t)aR * lda + kk);
                v.x += u.x; v.y += u.y; v.z += u.z; v.w += u.w;
            }
            if (NSRC > 2) {
                float4 u = *(const float4*)(A2 + (size_t)aR * lda + kk);
                v.x += u.x; v.y += u.y; v.z += u.z; v.w += u.w;
            }
            if (NSRC > 3) {
                float4 u = *(const float4*)(A3 + (size_t)aR * lda + kk);
                v.x += u.x; v.y += u.y; v.z += u.z; v.w += u.w;
            }
            if (ABIAS) {
                v.x += abias[kk]; v.y += abias[kk + 1];
                v.z += abias[kk + 2]; v.w += abias[kk + 3];
            }
            if (ATANH) {
                v.x = tanhf(v.x); v.y = tanhf(v.y);
                v.z = tanhf(v.z); v.w = tanhf(v.w);
            }
            ar[hh * 4 + 0] = v.x; ar[hh * 4 + 1] = v.y;
            ar[hh * 4 + 2] = v.z; ar[hh * 4 + 3] = v.w;
        }
    };
    auto loadB = [&](int k0) {
        if (BMODE == 0) {
            float4 v = *(const float4*)(Wsrc + (size_t)(k0 + bK) * wld + bC);
            bw[0] = v.x; bw[1] = v.y; bw[2] = v.z; bw[3] = v.w;
        } else if (BMODE == 1) {
            #pragma unroll
            for (int j = 0; j < 4; j++) {
                int c = bC + j;
                bw[j] = (c < wvalid) ? Wsrc[(size_t)(k0 + bK) * wld + c] : 0.f;
            }
        } else {
            float4 v = *(const float4*)(Wsrc + (size_t)tnN * wld + k0 + tm4);
            bw[0] = v.x; bw[1] = v.y; bw[2] = v.z; bw[3] = v.w;
        }
    };
    auto storeAB = [&](int buf) {
        float* Ab = As + buf * 2112;
        #pragma unroll
        for (int u = 0; u < 8; u++) Ab[(aK + u) * 132 + aR] = ar[u];
        float* Bb = Bs + buf * 1024;
        if (BMODE == 2) {
            #pragma unroll
            for (int u = 0; u < 4; u++) Bb[(tm4 + u) * 64 + tnN] = bw[u];
        } else {
            float4 v = make_float4(bw[0], bw[1], bw[2], bw[3]);
            *(float4*)&Bb[bK * 64 + bC] = v;
        }
    };

    float acc[8][4] = {};
    loadA(0); loadB(0); storeAB(0);
    __syncthreads();
    int buf = 0;
    for (int k0 = 0; k0 < K; k0 += 16) {
        bool more = (k0 + 16) < K;
        if (more) { loadA(k0 + 16); loadB(k0 + 16); }
        float* Ab = As + buf * 2112;
        float* Bb = Bs + buf * 1024;
        #pragma unroll
        for (int kk = 0; kk < 16; kk++) {
            float4 a0 = *(const float4*)&Ab[kk * 132 + ty * 8];
            float4 a1 = *(const float4*)&Ab[kk * 132 + ty * 8 + 4];
            float4 b4 = *(const float4*)&Bb[kk * 64 + tx * 4];
            float av[8] = {a0.x, a0.y, a0.z, a0.w, a1.x, a1.y, a1.z, a1.w};
            float bv[4] = {b4.x, b4.y, b4.z, b4.w};
            #pragma unroll
            for (int i = 0; i < 8; i++)
                #pragma unroll
                for (int j = 0; j < 4; j++)
                    acc[i][j] = fmaf(av[i], bv[j], acc[i][j]);
        }
        if (more) storeAB(buf ^ 1);
        __syncthreads();
        buf ^= 1;
    }
    #pragma unroll
    for (int j = 0; j < 4; j++) {
        int c = tx * 4 + j;
        if (BMODE != 1 || c < wvalid) {
            float bv = cbias ? cbias[c] : 0.f;
            #pragma unroll
            for (int i = 0; i < 8; i++)
                Cdst[(size_t)(ty * 8 + i) * ldc + c] = acc[i][j] + bv;
        }
    }
}

// ---------------- memory update tile (dual-B, fused EA activation) ----------
// mem[n0:+128, m0:+64] = mem*(1 - ww^T e / B) + ww^T a / B, K = batch = 256.
__device__ void tile_memupd(float* sh, const float* __restrict__ bea, int n0, int m0)
{
    float* As = sh;            // ww transposed [2][16][132]
    float* Be = sh + 4224;     // e [2][16][64]
    float* Ba = sh + 6272;     // a [2][16][64]
    const int tid = threadIdx.x;
    const int bk = tid >> 4, nR8 = (tid & 15) * 8;
    const int eK = tid >> 4, eC = (tid & 15) * 4;
    const int ty = tid >> 4, tx = tid & 15;
    float ar[8], ev[4], av[4];

    auto loadA = [&](int b0) {
        #pragma unroll
        for (int hh = 0; hh < 2; hh++) {
            float4 v = *(const float4*)(g_ww + (size_t)(b0 + bk) * NN + n0 + nR8 + hh * 4);
            ar[hh * 4 + 0] = v.x; ar[hh * 4 + 1] = v.y;
            ar[hh * 4 + 2] = v.z; ar[hh * 4 + 3] = v.w;
        }
    };
    auto loadB = [&](int b0) {
        size_t ro = (size_t)(b0 + eK) * (2 * MM);
        float4 e0 = *(const float4*)(g_EA0 + ro + m0 + eC);
        float4 e1 = *(const float4*)(g_EA1 + ro + m0 + eC);
        float4 a0 = *(const float4*)(g_EA0 + ro + MM + m0 + eC);
        float4 a1 = *(const float4*)(g_EA1 + ro + MM + m0 + eC);
        ev[0] = sigmoidf_(e0.x + e1.x + bea[m0 + eC + 0]);
        ev[1] = sigmoidf_(e0.y + e1.y + bea[m0 + eC + 1]);
        ev[2] = sigmoidf_(e0.z + e1.z + bea[m0 + eC + 2]);
        ev[3] = sigmoidf_(e0.w + e1.w + bea[m0 + eC + 3]);
        av[0] = tanhf(a0.x + a1.x + bea[MM + m0 + eC + 0]);
        av[1] = tanhf(a0.y + a1.y + bea[MM + m0 + eC + 1]);
        av[2] = tanhf(a0.z + a1.z + bea[MM + m0 + eC + 2]);
        av[3] = tanhf(a0.w + a1.w + bea[MM + m0 + eC + 3]);
    };
    auto storeAB = [&](int buf) {
        float* Ab = As + buf * 2112;
        #pragma unroll
        for (int hh = 0; hh < 2; hh++)
            *(float4*)&Ab[bk * 132 + nR8 + hh * 4] =
                make_float4(ar[hh * 4], ar[hh * 4 + 1], ar[hh * 4 + 2], ar[hh * 4 + 3]);
        *(float4*)&Be[buf * 1024 + eK * 64 + eC] = make_float4(ev[0], ev[1], ev[2], ev[3]);
        *(float4*)&Ba[buf * 1024 + eK * 64 + eC] = make_float4(av[0], av[1], av[2], av[3]);
    };

    float ae[8][4] = {}, aa[8][4] = {};
    loadA(0); loadB(0); storeAB(0);
    __syncthreads();
    int buf = 0;
    for (int b0 = 0; b0 < B_; b0 += 16) {
        bool more = (b0 + 16) < B_;
        if (more) { loadA(b0 + 16); loadB(b0 + 16); }
        float* Ab = As + buf * 2112;
        float* Eb = Be + buf * 1024;
        float* Bb = Ba + buf * 1024;
        #pragma unroll
        for (int kk = 0; kk < 16; kk++) {
            float4 a0 = *(const float4*)&Ab[kk * 132 + ty * 8];      // NOTE: rows = n, stored by loadA as [bk][n]
            float4 a1 = *(const float4*)&Ab[kk * 132 + ty * 8 + 4];
            float4 e4 = *(const float4*)&Eb[kk * 64 + tx * 4];
            float4 b4 = *(const float4*)&Bb[kk * 64 + tx * 4];
            float wv[8] = {a0.x, a0.y, a0.z, a0.w, a1.x, a1.y, a1.z, a1.w};
            float evv[4] = {e4.x, e4.y, e4.z, e4.w};
            float avv[4] = {b4.x, b4.y, b4.z, b4.w};
            #pragma unroll
            for (int i = 0; i < 8; i++)
                #pragma unroll
                for (int j = 0; j < 4; j++) {
                    ae[i][j] = fmaf(wv[i], evv[j], ae[i][j]);
                    aa[i][j] = fmaf(wv[i], avv[j], aa[i][j]);
                }
        }
        if (more) storeAB(buf ^ 1);
        __syncthreads();
        buf ^= 1;
    }
    const float invB = 1.f / (float)B_;
    #pragma unroll
    for (int i = 0; i < 8; i++)
        #pragma unroll
        for (int j = 0; j < 4; j++) {
            size_t idx = (size_t)(n0 + ty * 8 + i) * MM + m0 + tx * 4 + j;
            float mo = g_mem[idx];
            g_mem[idx] = mo * (1.f - ae[i][j] * invB) + aa[i][j] * invB;
        }
}

// ---------------- per-row memory norms (32 rows per job) ----------------
__device__ void norm_job(int nj) {
    const int t = threadIdx.x;
    const int row = nj * 32 + (t >> 3);
    const int p = t & 7;
    const float* rp = g_mem + (size_t)row * MM;
    float s = 0.f;
    #pragma unroll
    for (int u = 0; u < 64; u++) {
        float v = rp[p + u * 8];
        s += v * v;
    }
    s += __shfl_xor_sync(0xffffffffu, s, 1);
    s += __shfl_xor_sync(0xffffffffu, s, 2);
    s += __shfl_xor_sync(0xffffffffu, s, 4);
    if (p == 0) g_memnorm[row] = sqrtf(s);
    __syncthreads();
}

// ---------------- addressing job (per batch row b, head z) ----------------
__device__ void addr_job(float* sh, int b, int z) {
    float* swg  = sh;
    float* red  = sh + 1024;
    float* scal = sh + 1064;
    const float* P0 = (z ? g_Pr0 : g_Pw0) + (size_t)b * PSTR;
    const float* P1 = (z ? g_Pr1 : g_Pw1) + (size_t)b * PSTR;
    const float* C0 = (z ? g_Cr0 : g_Cw0) + (size_t)b * NN;
    const float* C1 = (z ? g_Cr1 : g_Cw1) + (size_t)b * NN;
    float* wrow = (z ? g_wr : g_ww) + (size_t)b * NN;
    const int tid = threadIdx.x;
    __syncthreads();

    float s = 0.f;
    #pragma unroll
    for (int u = 0; u < 2; u++) {
        int i = tid + u * 256;
        float k = tanhf(P0[i] + P1[i]);
        s += k * k;
    }
    s = blockSum(s, red);
    if (tid == 0) {
        scal[6] = sqrtf(s) + EPS;
        float p0 = P0[MM] + P1[MM], p1 = P0[MM + 1] + P1[MM + 1];
        float p2 = P0[MM + 2] + P1[MM + 2], p3 = P0[MM + 3] + P1[MM + 3];
        float p4 = P0[MM + 4] + P1[MM + 4], p5 = P0[MM + 5] + P1[MM + 5];
        scal[0] = softplusf_(p0);
        scal[1] = sigmoidf_(p1);
        float m = fmaxf(p2, fmaxf(p3, p4));
        float e0 = expf(p2 - m), e1 = expf(p3 - m), e2 = expf(p4 - m);
        float ss = e0 + e1 + e2;
        scal[2] = e0 / ss; scal[3] = e1 / ss; scal[4] = e2 / ss;
        scal[5] = 1.f + softplusf_(p5);
    }
    __syncthreads();
    float beta = scal[0], gg = scal[1], s0 = scal[2], s1 = scal[3], s2 = scal[4];
    float gamma = scal[5], knorm = scal[6];

    float v[4];
    float mx = -3.4e38f;
    #pragma unroll
    for (int u = 0; u < 4; u++) {
        int n = tid + u * 256;
        float sc = beta * (C0[n] + C1[n]) / (knorm * (g_memnorm[n] + EPS));
        v[u] = sc;
        mx = fmaxf(mx, sc);
    }
    mx = blockMax(mx, red);
    float se = 0.f;
    #pragma unroll
    for (int u = 0; u < 4; u++) {
        v[u] = expf(v[u] - mx);
        se += v[u];
    }
    se = blockSum(se, red);
    float inv = 1.f / se;
    #pragma unroll
    for (int u = 0; u < 4; u++) {
        int n = tid + u * 256;
        float wc = v[u] * inv;
        swg[n] = gg * wc + (1.f - gg) * wrow[n];
    }
    __syncthreads();
    float S = 0.f;
    #pragma unroll
    for (int u = 0; u < 4; u++) {
        int n = tid + u * 256;
        float wt = s1 * swg[n] + s0 * swg[(n + 1) & (NN - 1)] + s2 * swg[(n - 1) & (NN - 1)];
        v[u] = powf(wt, gamma);
        S += v[u];
    }
    S = blockSum(S, red);
    float invS = 1.f / (S + EPS);
    #pragma unroll
    for (int u = 0; u < 4; u++)
        wrow[tid + u * 256] = v[u] * invS;
    __syncthreads();
}

// ---------------- out-merge job ----------------
__device__ void outmerge_job(const float* __restrict__ bo, float* __restrict__ out,
                             int t, int j) {
    for (int l = threadIdx.x; l < 8192; l += 256) {
        int e = j * 8192 + l;
        int b = e >> 9, o = e & 511;
        out[((size_t)b * T_ + t) * OO + o] = sigmoidf_(g_op0[e] + g_op1[e] + bo[o]);
    }
    __syncthreads();
}

// ---------------- the megakernel ----------------
__global__ void __launch_bounds__(256) ntm_mega(
    const float* __restrict__ x,
    const float* __restrict__ mem0, const float* __restrict__ wr0,
    const float* __restrict__ ww0, const float* __restrict__ h0,
    const float* __restrict__ Wx, const float* __restrict__ Wr,
    const float* __restrict__ bh,
    const float* __restrict__ Whr, const float* __restrict__ bhr,
    const float* __restrict__ Whw, const float* __restrict__ bhw,
    const float* __restrict__ Wea, const float* __restrict__ bea,
    const float* __restrict__ Wo, const float* __restrict__ bo,
    float* __restrict__ out)
{
    __shared__ float sh[8608];
    unsigned sense = 0;
    const int bid = blockIdx.x;
    const int tid = threadIdx.x;
    const int gthread = bid * 256 + tid;

    // INIT: copy state + hx(t=0, parity 0) + EA(from h0)
    for (int i = gthread; i < NN * MM; i += NB * 256) g_mem[i] = mem0[i];
    for (int i = gthread; i < B_ * NN; i += NB * 256) {
        g_wr[i] = wr0[i];
        g_ww[i] = ww0[i];
    }
    for (int j = bid; j < 96; j += NB) {
        if (j < 32) {  // hx(0): ks = j>>4, tiles: rows 2 x cols 8
            int ks = j >> 4, jj = j & 15;
            int row0 = (jj & 1) * 128, col0 = (jj >> 1) * 64;
            tile_gemm<1, false, false, 0>(sh,
                x + (size_t)row0 * (T_ * I_) + ks * 256, nullptr, nullptr, nullptr,
                nullptr, T_ * I_,
                Wx + (size_t)(ks * 256) * H_ + col0, H_, 64, nullptr,
                g_hxp[0][ks] + (size_t)row0 * H_ + col0, H_, 256);
        } else {       // EA(0) from h0: j-32 in [0,64): ks = (j-32)>>5, 32 tiles
            int jj = j - 32;
            int ks = jj >> 5, j2 = jj & 31;
            int row0 = (j2 & 1) * 128, col0 = (j2 >> 1) * 64;
            float* dst = ks ? g_EA1 : g_EA0;
            tile_gemm<1, false, false, 0>(sh,
                h0 + (size_t)row0 * H_ + ks * 256, nullptr, nullptr, nullptr,
                nullptr, H_,
                Wea + (size_t)(ks * 256) * (2 * MM) + col0, 2 * MM, 64, nullptr,
                dst + (size_t)row0 * (2 * MM) + col0, 2 * MM, 256);
        }
    }
    gbar(sense);                                              // 1

    for (int t = 0; t < T_; t++) {
        const int p = t & 1, pn = (t + 1) & 1;
        const float* hx0 = g_hxp[p][0];
        const float* hx1 = g_hxp[p][1];

        // P1: memory erase/add, 64 tiles (n 8 x m 8)
        for (int j = bid; j < 64; j += NB)
            tile_memupd(sh, bea, (j >> 3) * 128, (j & 7) * 64);
        gbar(sense);

        // P2: r partials rp[q] = wr[:, q*256:+256] @ mem[q*256:+256, :], 64 tiles
        for (int j = bid; j < 64; j += NB) {
            int q = j >> 4, jj = j & 15;
            int row0 = (jj & 1) * 128, col0 = (jj >> 1) * 64;
            tile_gemm<1, false, false, 0>(sh,
                g_wr + (size_t)row0 * NN + q * 256, nullptr, nullptr, nullptr,
                nullptr, NN,
                g_mem + (size_t)(q * 256) * MM + col0, MM, 64, nullptr,
                g_rp[q] + (size_t)row0 * MM + col0, MM, 256);
        }
        gbar(sense);

        // P3: hr partials (A = rp0+rp1+rp2+rp3), 32 tiles; norms 32 jobs
        for (int j = bid; j < 64; j += NB) {
            if (j < 32) {
                int ks = j >> 4, jj = j & 15;
                int row0 = (jj & 1) * 128, col0 = (jj >> 1) * 64;
                size_t ao = (size_t)row0 * MM + ks * 256;
                tile_gemm<4, false, false, 0>(sh,
                    g_rp[0] + ao, g_rp[1] + ao, g_rp[2] + ao, g_rp[3] + ao,
                    nullptr, MM,
                    Wr + (size_t)(ks * 256) * H_ + col0, H_, 64, nullptr,
                    g_hrp[ks] + (size_t)row0 * H_ + col0, H_, 256);
            } else {
                norm_job(j - 32);
            }
        }
        gbar(sense);

        // P4: Pw (36) + Pr (36) + out (32); A = tanh(hx0+hx1+hr0+hr1+bh)
        for (int j = bid; j < 104; j += NB) {
            if (j < 72) {
                int head = j / 36, jj = j % 36;
                int ks = jj / 18, j2 = jj % 18;
                int row0 = (j2 % 2) * 128, ct = j2 / 2;
                int col0 = ct * 64;
                int wvalid = (MM + 6) - col0; if (wvalid > 64) wvalid = 64;
                const float* Wh = head ? Whr : Whw;
                const float* bp = head ? bhr : bhw;
                float* dst = head ? (ks ? g_Pr1 : g_Pr0) : (ks ? g_Pw1 : g_Pw0);
                size_t ao = (size_t)row0 * H_ + ks * 256;
                tile_gemm<4, true, true, 1>(sh,
                    hx0 + ao, hx1 + ao, g_hrp[0] + ao, g_hrp[1] + ao,
                    bh + ks * 256, H_,
                    Wh + (size_t)(ks * 256) * (MM + 6) + col0, MM + 6, wvalid,
                    (ks == 0) ? (bp + col0) : nullptr,
                    dst + (size_t)row0 * PSTR + col0, PSTR, 256);
            } else {
                int jj = j - 72;
                int ks = jj >> 4, j2 = jj & 15;
                int row0 = (j2 & 1) * 128, col0 = (j2 >> 1) * 64;
                size_t ao = (size_t)row0 * H_ + ks * 256;
                tile_gemm<4, true, true, 0>(sh,
                    hx0 + ao, hx1 + ao, g_hrp[0] + ao, g_hrp[1] + ao,
                    bh + ks * 256, H_,
                    Wo + (size_t)(ks * 256) * OO + col0, OO, 64, nullptr,
                    (ks ? g_op1 : g_op0) + (size_t)row0 * OO + col0, OO, 256);
            }
        }
        gbar(sense);

        // P5: scores, 2 heads x 2 ksplit x (2 rows x 16 ncols) = 128 tiles
        for (int j = bid; j < 128; j += NB) {
            int z = j >> 6, jj = j & 63;
            int ks = jj >> 5, j2 = jj & 31;
            int row0 = (j2 & 1) * 128, n0 = (j2 >> 1) * 64;
            const float* P0 = (z ? g_Pr0 : g_Pw0) + (size_t)row0 * PSTR + ks * 256;
            const float* P1 = (z ? g_Pr1 : g_Pw1) + (size_t)row0 * PSTR + ks * 256;
            float* Cd = (z ? (ks ? g_Cr1 : g_Cr0) : (ks ? g_Cw1 : g_Cw0));
            tile_gemm<2, true, false, 2>(sh,
                P0, P1, nullptr, nullptr, nullptr, PSTR,
                g_mem + (size_t)n0 * MM + ks * 256, MM, 64, nullptr,
                Cd + (size_t)row0 * NN + n0, NN, 256);
        }
        gbar(sense);

        // P6: EA(next, 64) + hx(t+1, 32) heavy; addr (512) + out-merge (16) light
        if (t < T_ - 1) {
            for (int j = bid; j < 96; j += NB) {
                if (j < 64) {
                    int ks = j >> 5, j2 = j & 31;
                    int row0 = (j2 & 1) * 128, col0 = (j2 >> 1) * 64;
                    size_t ao = (size_t)row0 * H_ + ks * 256;
                    tile_gemm<4, true, true, 0>(sh,
                        hx0 + ao, hx1 + ao, g_hrp[0] + ao, g_hrp[1] + ao,
                        bh + ks * 256, H_,
                        Wea + (size_t)(ks * 256) * (2 * MM) + col0, 2 * MM, 64, nullptr,
                        (ks ? g_EA1 : g_EA0) + (size_t)row0 * (2 * MM) + col0,
                        2 * MM, 256);
                } else {
                    int jj = j - 64;
                    int ks = jj >> 4, j2 = jj & 15;
                    int row0 = (j2 & 1) * 128, col0 = (j2 >> 1) * 64;
                    tile_gemm<1, false, false, 0>(sh,
                        x + (size_t)row0 * (T_ * I_) + (t + 1) * I_ + ks * 256,
                        nullptr, nullptr, nullptr, nullptr, T_ * I_,
                        Wx + (size_t)(ks * 256) * H_ + col0, H_, 64, nullptr,
                        g_hxp[pn][ks] + (size_t)row0 * H_ + col0, H_, 256);
                }
            }
        }
        for (int j = bid; j < 528; j += NB) {
            if (j < 512) addr_job(sh, j & 255, j >> 8);
            else outmerge_job(bo, out, t, j - 512);
        }
        gbar(sense);
    }
    gbar(sense);   // total barriers: 1 + 6*128 + 1 = 770 (even)
}

extern "C" void kernel_launch(void* const* d_in, const int* in_sizes, int n_in,
                              void* d_out, int out_size)
{
    (void)in_sizes; (void)n_in; (void)out_size;
    ntm_mega<<<NB, 256>>>(
        (const float*)d_in[0],  (const float*)d_in[1],  (const float*)d_in[2],
        (const float*)d_in[3],  (const float*)d_in[4],  (const float*)d_in[5],
        (const float*)d_in[6],  (const float*)d_in[7],  (const float*)d_in[8],
        (const float*)d_in[9],  (const float*)d_in[10], (const float*)d_in[11],
        (const float*)d_in[12], (const float*)d_in[13], (const float*)d_in[14],
        (const float*)d_in[15], (float*)d_out);
}

// round 4
// speedup vs baseline: 1.4291x; 1.3080x over previous
#include <cuda_runtime.h>
#include <math.h>

#define B_   256
#define T_   128
#define I_   512
#define H_   512
#define NN   1024
#define MM   512
#define OO   512
#define PSTR 520
#define EPS  1e-8f
#define NB   144
#define NT   512

// ---------------- persistent device state ----------------
__device__ __align__(256) float g_mem[NN * MM];
__device__ __align__(256) float g_wr[B_ * NN];
__device__ __align__(256) float g_ww[B_ * NN];
__device__ __align__(256) float g_EA0[B_ * 2 * MM];
__device__ __align__(256) float g_EA1[B_ * 2 * MM];
__device__ __align__(256) float g_rp[4][B_ * MM];
__device__ __align__(256) float g_hx[2][B_ * H_];
__device__ __align__(256) float g_hr[2][B_ * H_];
__device__ __align__(256) float g_Pw[B_ * PSTR];
__device__ __align__(256) float g_Pr[B_ * PSTR];
__device__ __align__(256) float g_Cw0[B_ * NN];
__device__ __align__(256) float g_Cw1[B_ * NN];
__device__ __align__(256) float g_Cr0[B_ * NN];
__device__ __align__(256) float g_Cr1[B_ * NN];
__device__ __align__(256) float g_memnorm[NN];
__device__ unsigned g_cnt;
__device__ volatile unsigned g_sense;

// ---------------- helpers ----------------
__device__ __forceinline__ float sigmoidf_(float x) { return 1.f / (1.f + expf(-x)); }
__device__ __forceinline__ float softplusf_(float x) {
    return fmaxf(x, 0.f) + log1pf(expf(-fabsf(x)));
}
__device__ __forceinline__ float warpSum(float v) {
    #pragma unroll
    for (int o = 16; o; o >>= 1) v += __shfl_xor_sync(0xffffffffu, v, o);
    return v;
}
__device__ __forceinline__ float warpMax(float v) {
    #pragma unroll
    for (int o = 16; o; o >>= 1) v = fmaxf(v, __shfl_xor_sync(0xffffffffu, v, o));
    return v;
}
__device__ float blockSum(float v, float* red) {
    int lane = threadIdx.x & 31, w = threadIdx.x >> 5;
    v = warpSum(v);
    if (lane == 0) red[w] = v;
    __syncthreads();
    if (threadIdx.x == 0) {
        float s = 0.f;
        #pragma unroll
        for (int i = 0; i < 16; i++) s += red[i];
        red[16] = s;
    }
    __syncthreads();
    float r = red[16];
    __syncthreads();
    return r;
}
__device__ float blockMax(float v, float* red) {
    int lane = threadIdx.x & 31, w = threadIdx.x >> 5;
    v = warpMax(v);
    if (lane == 0) red[w] = v;
    __syncthreads();
    if (threadIdx.x == 0) {
        float m = red[0];
        #pragma unroll
        for (int i = 1; i < 16; i++) m = fmaxf(m, red[i]);
        red[16] = m;
    }
    __syncthreads();
    float r = red[16];
    __syncthreads();
    return r;
}

__device__ __forceinline__ void gbar(unsigned& sense) {
    __threadfence();
    __syncthreads();
    if (threadIdx.x == 0) {
        unsigned ns = sense ^ 1u;
        if (atomicAdd(&g_cnt, 1u) == NB - 1u) {
            atomicExch(&g_cnt, 0u);
            __threadfence();
            g_sense = ns;
        } else {
            while (g_sense != ns) __nanosleep(32);
        }
        sense = ns;
        __threadfence();
    }
    __syncthreads();
}

// ---------------- 64x64 double-buffered GEMM tile (512 threads) ----------
// acc 4x2 per thread. A built from up to 4 summed sources (+k-bias, +tanh).
// BMODE 0: W row-major float4; 1: row-major scalar + col guard (wvalid);
// BMODE 2: B[k][n] = Wsrc[n*wld + k] (transposed source, e.g. mem^T).
// ACT 0: none, 2: sigmoid. All pointers pre-offset to (row0/kofs/col0).
template<int NSRC, bool ATANH, bool ABIAS, int ACT, int BMODE>
__device__ void tile_gemm(
    float* sh,
    const float* __restrict__ A0, const float* __restrict__ A1,
    const float* __restrict__ A2, const float* __restrict__ A3,
    const float* __restrict__ abias, int lda,
    const float* __restrict__ Wsrc, int wld, int wvalid,
    const float* __restrict__ cbias,
    float* __restrict__ Cdst, int ldc, int K)
{
    float* As = sh;            // [2][32][68]
    float* Bs = sh + 4352;     // [2][32][68]
    const int tid = threadIdx.x;
    const int aR = tid >> 3, aK4 = (tid & 7) * 4;
    const int bK = tid >> 4, bC = (tid & 15) * 4;
    const int b2n = tid >> 3, b2k = (tid & 7) * 4;
    const int ty = tid >> 5, tx = tid & 31;
    float ar[4], bw[4];

    auto loadA = [&](int k0) {
        int kk = k0 + aK4;
        float4 v = *(const float4*)(A0 + (size_t)aR * lda + kk);
        if (NSRC > 1) {
            float4 u = *(const float4*)(A1 + (size_t)aR * lda + kk);
            v.x += u.x; v.y += u.y; v.z += u.z; v.w += u.w;
        }
        if (NSRC > 2) {
            float4 u = *(const float4*)(A2 + (size_t)aR * lda + kk);
            v.x += u.x; v.y += u.y; v.z += u.z; v.w += u.w;
        }
        if (NSRC > 3) {
            float4 u = *(const float4*)(A3 + (size_t)aR * lda + kk);
            v.x += u.x; v.y += u.y; v.z += u.z; v.w += u.w;
        }
        if (ABIAS) {
            v.x += abias[kk]; v.y += abias[kk + 1];
            v.z += abias[kk + 2]; v.w += abias[kk + 3];
        }
        if (ATANH) {
            v.x = tanhf(v.x); v.y = tanhf(v.y);
            v.z = tanhf(v.z); v.w = tanhf(v.w);
        }
        ar[0] = v.x; ar[1] = v.y; ar[2] = v.z; ar[3] = v.w;
    };
    auto loadB = [&](int k0) {
        if (BMODE == 0) {
            float4 v = *(const float4*)(Wsrc + (size_t)(k0 + bK) * wld + bC);
            bw[0] = v.x; bw[1] = v.y; bw[2] = v.z; bw[3] = v.w;
        } else if (BMODE == 1) {
            #pragma unroll
            for (int u = 0; u < 4; u++) {
                int c = bC + u;
                bw[u] = (c < wvalid) ? Wsrc[(size_t)(k0 + bK) * wld + c] : 0.f;
            }
        } else {
            float4 v = *(const float4*)(Wsrc + (size_t)b2n * wld + k0 + b2k);
            bw[0] = v.x; bw[1] = v.y; bw[2] = v.z; bw[3] = v.w;
        }
    };
    auto storeAB = [&](int buf) {
        float* Ab = As + buf * 2176;
        #pragma unroll
        for (int u = 0; u < 4; u++) Ab[(aK4 + u) * 68 + aR] = ar[u];
        float* Bb = Bs + buf * 2176;
        if (BMODE == 2) {
            #pragma unroll
            for (int u = 0; u < 4; u++) Bb[(b2k + u) * 68 + b2n] = bw[u];
        } else {
            *(float4*)&Bb[bK * 68 + bC] = make_float4(bw[0], bw[1], bw[2], bw[3]);
        }
    };

    float acc[4][2] = {};
    loadA(0); loadB(0); storeAB(0);
    __syncthreads();
    int buf = 0;
    for (int k0 = 0; k0 < K; k0 += 32) {
        bool more = (k0 + 32) < K;
        if (more) { loadA(k0 + 32); loadB(k0 + 32); }
        float* Ab = As + buf * 2176;
        float* Bb = Bs + buf * 2176;
        #pragma unroll
        for (int kk = 0; kk < 32; kk++) {
            float4 a4 = *(const float4*)&Ab[kk * 68 + ty * 4];
            float2 b2 = *(const float2*)&Bb[kk * 68 + tx * 2];
            float av[4] = {a4.x, a4.y, a4.z, a4.w};
            float bv[2] = {b2.x, b2.y};
            #pragma unroll
            for (int i = 0; i < 4; i++)
                #pragma unroll
                for (int j = 0; j < 2; j++)
                    acc[i][j] = fmaf(av[i], bv[j], acc[i][j]);
        }
        if (more) storeAB(buf ^ 1);
        __syncthreads();
        buf ^= 1;
    }
    #pragma unroll
    for (int j = 0; j < 2; j++) {
        int c = tx * 2 + j;
        if (BMODE != 1 || c < wvalid) {
            float bv = cbias ? cbias[c] : 0.f;
            #pragma unroll
            for (int i = 0; i < 4; i++) {
                float v = acc[i][j] + bv;
                if (ACT == 2) v = sigmoidf_(v);
                Cdst[(size_t)(ty * 4 + i) * ldc + c] = v;
            }
        }
    }
}

// ---------------- memory update tile 64n x 64m (dual acc, K = B = 256) ----
__device__ void tile_memupd(float* sh, const float* __restrict__ bea, int n0, int m0)
{
    float* Ws  = sh;            // [2][32][68]
    float* Es  = sh + 4352;
    float* Aas = sh + 8704;
    const int tid = threadIdx.x;
    const int wK = tid >> 4, wC = (tid & 15) * 4;
    const int ty = tid >> 5, tx = tid & 31;
    float wr_[4], ev[4], av[4];

    auto loadAll = [&](int b0) {
        float4 w = *(const float4*)(g_ww + (size_t)(b0 + wK) * NN + n0 + wC);
        wr_[0] = w.x; wr_[1] = w.y; wr_[2] = w.z; wr_[3] = w.w;
        size_t ro = (size_t)(b0 + wK) * (2 * MM);
        float4 e0 = *(const float4*)(g_EA0 + ro + m0 + wC);
        float4 e1 = *(const float4*)(g_EA1 + ro + m0 + wC);
        float4 a0 = *(const float4*)(g_EA0 + ro + MM + m0 + wC);
        float4 a1 = *(const float4*)(g_EA1 + ro + MM + m0 + wC);
        ev[0] = sigmoidf_(e0.x + e1.x + bea[m0 + wC + 0]);
        ev[1] = sigmoidf_(e0.y + e1.y + bea[m0 + wC + 1]);
        ev[2] = sigmoidf_(e0.z + e1.z + bea[m0 + wC + 2]);
        ev[3] = sigmoidf_(e0.w + e1.w + bea[m0 + wC + 3]);
        av[0] = tanhf(a0.x + a1.x + bea[MM + m0 + wC + 0]);
        av[1] = tanhf(a0.y + a1.y + bea[MM + m0 + wC + 1]);
        av[2] = tanhf(a0.z + a1.z + bea[MM + m0 + wC + 2]);
        av[3] = tanhf(a0.w + a1.w + bea[MM + m0 + wC + 3]);
    };
    auto storeAll = [&](int buf) {
        *(float4*)&Ws [buf * 2176 + wK * 68 + wC] = make_float4(wr_[0], wr_[1], wr_[2], wr_[3]);
        *(float4*)&Es [buf * 2176 + wK * 68 + wC] = make_float4(ev[0], ev[1], ev[2], ev[3]);
        *(float4*)&Aas[buf * 2176 + wK * 68 + wC] = make_float4(av[0], av[1], av[2], av[3]);
    };

    float ae[4][2] = {}, aa[4][2] = {};
    loadAll(0); storeAll(0);
    __syncthreads();
    int buf = 0;
    for (int b0 = 0; b0 < B_; b0 += 32) {
        bool more = (b0 + 32) < B_;
        if (more) loadAll(b0 + 32);
        float* Wb = Ws + buf * 2176;
        float* Eb = Es + buf * 2176;
        float* Ab = Aas + buf * 2176;
        #pragma unroll
        for (int kk = 0; kk < 32; kk++) {
            float4 w4 = *(const float4*)&Wb[kk * 68 + ty * 4];
            float2 e2 = *(const float2*)&Eb[kk * 68 + tx * 2];
            float2 a2 = *(const float2*)&Ab[kk * 68 + tx * 2];
            float wv[4] = {w4.x, w4.y, w4.z, w4.w};
            float evv[2] = {e2.x, e2.y};
            float avv[2] = {a2.x, a2.y};
            #pragma unroll
            for (int i = 0; i < 4; i++)
                #pragma unroll
                for (int j = 0; j < 2; j++) {
                    ae[i][j] = fmaf(wv[i], evv[j], ae[i][j]);
                    aa[i][j] = fmaf(wv[i], avv[j], aa[i][j]);
                }
        }
        if (more) storeAll(buf ^ 1);
        __syncthreads();
        buf ^= 1;
    }
    const float invB = 1.f / (float)B_;
    #pragma unroll
    for (int i = 0; i < 4; i++)
        #pragma unroll
        for (int j = 0; j < 2; j++) {
            size_t idx = (size_t)(n0 + ty * 4 + i) * MM + m0 + tx * 2 + j;
            float mo = g_mem[idx];
            g_mem[idx] = mo * (1.f - ae[i][j] * invB) + aa[i][j] * invB;
        }
}

// ---------------- per-row memory norms (64 rows per job) ----------------
__device__ void norm_job(int nj) {
    const int t = threadIdx.x;
    const int row = nj * 64 + (t >> 3);
    const int p = t & 7;
    const float* rp = g_mem + (size_t)row * MM;
    float s = 0.f;
    #pragma unroll
    for (int u = 0; u < 64; u++) {
        float v = rp[p + u * 8];
        s += v * v;
    }
    s += __shfl_xor_sync(0xffffffffu, s, 1);
    s += __shfl_xor_sync(0xffffffffu, s, 2);
    s += __shfl_xor_sync(0xffffffffu, s, 4);
    if (p == 0) g_memnorm[row] = sqrtf(s);
}

// ---------------- addressing job (batch row b, head z), 512 threads -------
__device__ void addr_job(float* sh, int b, int z) {
    float* swg  = sh;            // [0,1024)
    float* red  = sh + 1024;     // 17
    float* scal = sh + 1044;     // 7
    const float* P = (z ? g_Pr : g_Pw) + (size_t)b * PSTR;
    const float* C0 = (z ? g_Cr0 : g_Cw0) + (size_t)b * NN;
    const float* C1 = (z ? g_Cr1 : g_Cw1) + (size_t)b * NN;
    float* wrow = (z ? g_wr : g_ww) + (size_t)b * NN;
    const int tid = threadIdx.x;
    __syncthreads();

    float kx = tanhf(P[tid]);                 // MM == NT
    float s = blockSum(kx * kx, red);
    if (tid == 0) {
        scal[6] = sqrtf(s) + EPS;
        float p0 = P[MM], p1 = P[MM + 1], p2 = P[MM + 2];
        float p3 = P[MM + 3], p4 = P[MM + 4], p5 = P[MM + 5];
        scal[0] = softplusf_(p0);
        scal[1] = sigmoidf_(p1);
        float m = fmaxf(p2, fmaxf(p3, p4));
        float e0 = expf(p2 - m), e1 = expf(p3 - m), e2 = expf(p4 - m);
        float ss = e0 + e1 + e2;
        scal[2] = e0 / ss; scal[3] = e1 / ss; scal[4] = e2 / ss;
        scal[5] = 1.f + softplusf_(p5);
    }
    __syncthreads();
    float beta = scal[0], gg = scal[1], s0 = scal[2], s1 = scal[3], s2 = scal[4];
    float gamma = scal[5], knorm = scal[6];

    float v[2];
    float mx = -3.4e38f;
    #pragma unroll
    for (int u = 0; u < 2; u++) {
        int n = tid + u * NT;
        float sc = beta * (C0[n] + C1[n]) / (knorm * (g_memnorm[n] + EPS));
        v[u] = sc;
        mx = fmaxf(mx, sc);
    }
    mx = blockMax(mx, red);
    float se = 0.f;
    #pragma unroll
    for (int u = 0; u < 2; u++) {
        v[u] = expf(v[u] - mx);
        se += v[u];
    }
    se = blockSum(se, red);
    float inv = 1.f / se;
    #pragma unroll
    for (int u = 0; u < 2; u++) {
        int n = tid + u * NT;
        swg[n] = gg * v[u] * inv + (1.f - gg) * wrow[n];
    }
    __syncthreads();
    float S = 0.f;
    #pragma unroll
    for (int u = 0; u < 2; u++) {
        int n = tid + u * NT;
        float wt = s1 * swg[n] + s0 * swg[(n + 1) & (NN - 1)] + s2 * swg[(n - 1) & (NN - 1)];
        v[u] = powf(wt, gamma);
        S += v[u];
    }
    S = blockSum(S, red);
    float invS = 1.f / (S + EPS);
    #pragma unroll
    for (int u = 0; u < 2; u++)
        wrow[tid + u * NT] = v[u] * invS;
    __syncthreads();
}

// ---------------- the megakernel ----------------
__global__ void __launch_bounds__(NT) ntm_mega(
    const float* __restrict__ x,
    const float* __restrict__ mem0, const float* __restrict__ wr0,
    const float* __restrict__ ww0, const float* __restrict__ h0,
    const float* __restrict__ Wx, const float* __restrict__ Wr,
    const float* __restrict__ bh,
    const float* __restrict__ Whr, const float* __restrict__ bhr,
    const float* __restrict__ Whw, const float* __restrict__ bhw,
    const float* __restrict__ Wea, const float* __restrict__ bea,
    const float* __restrict__ Wo, const float* __restrict__ bo,
    float* __restrict__ out)
{
    __shared__ float sh[13120];
    unsigned sense = 0;
    const int bid = blockIdx.x;
    const int tid = threadIdx.x;
    const int gthread = bid * NT + tid;

    // INIT: copy state; EA(0) from h0 (K-split 2)
    for (int i = gthread; i < NN * MM; i += NB * NT) g_mem[i] = mem0[i];
    for (int i = gthread; i < B_ * NN; i += NB * NT) {
        g_wr[i] = wr0[i];
        g_ww[i] = ww0[i];
    }
    for (int j = bid; j < 128; j += NB) {
        int ks = j >> 6, j2 = j & 63;
        int row0 = (j2 >> 4) * 64, col0 = (j2 & 15) * 64;
        tile_gemm<1, false, false, 0, 0>(sh,
            h0 + (size_t)row0 * H_ + ks * 256, nullptr, nullptr, nullptr,
            nullptr, H_,
            Wea + (size_t)(ks * 256) * (2 * MM) + col0, 2 * MM, 64, nullptr,
            (ks ? g_EA1 : g_EA0) + (size_t)row0 * (2 * MM) + col0, 2 * MM, 256);
    }
    gbar(sense);                                             // 1

    for (int t = 0; t < T_; t++) {
        // ---- P1: memory erase/add (128 jobs, 64x64, dual, K=256) ----
        for (int j = bid; j < 128; j += NB)
            tile_memupd(sh, bea, (j >> 3) * 64, (j & 7) * 64);
        gbar(sense);

        // ---- P2: r partials, ksplit 4 (128 jobs, K=256) ----
        for (int j = bid; j < 128; j += NB) {
            int ks = j >> 5, j2 = j & 31;
            int row0 = (j2 >> 3) * 64, col0 = (j2 & 7) * 64;
            tile_gemm<1, false, false, 0, 0>(sh,
                g_wr + (size_t)row0 * NN + ks * 256, nullptr, nullptr, nullptr,
                nullptr, NN,
                g_mem + (size_t)(ks * 256) * MM + col0, MM, 64, nullptr,
                g_rp[ks] + (size_t)row0 * MM + col0, MM, 256);
        }
        gbar(sense);

        // ---- P3: hr (64) + hx (64) + norms (16) = 144 jobs ----
        for (int j = bid; j < 144; j += NB) {
            if (j < 64) {
                int ks = j >> 5, j2 = j & 31;
                int row0 = (j2 >> 3) * 64, col0 = (j2 & 7) * 64;
                size_t ao = (size_t)row0 * MM + ks * 256;
                tile_gemm<4, false, false, 0, 0>(sh,
                    g_rp[0] + ao, g_rp[1] + ao, g_rp[2] + ao, g_rp[3] + ao,
                    nullptr, MM,
                    Wr + (size_t)(ks * 256) * H_ + col0, H_, 64, nullptr,
                    g_hr[ks] + (size_t)row0 * H_ + col0, H_, 256);
            } else if (j < 128) {
                int jj = j - 64;
                int ks = jj >> 5, j2 = jj & 31;
                int row0 = (j2 >> 3) * 64, col0 = (j2 & 7) * 64;
                tile_gemm<1, false, false, 0, 0>(sh,
                    x + (size_t)row0 * (T_ * I_) + (size_t)t * I_ + ks * 256,
                    nullptr, nullptr, nullptr, nullptr, T_ * I_,
                    Wx + (size_t)(ks * 256) * H_ + col0, H_, 64, nullptr,
                    g_hx[ks] + (size_t)row0 * H_ + col0, H_, 256);
            } else {
                norm_job(j - 128);
            }
        }
        gbar(sense);

        // ---- P4: Pw (36) + Pr (36) + out (32), K=512, h fused in A ----
        for (int j = bid; j < 104; j += NB) {
            if (j < 72) {
                int head = j / 36, jj = j % 36;
                int rt = jj / 9, ct = jj % 9;
                int row0 = rt * 64, col0 = ct * 64;
                int wvalid = (MM + 6) - col0; if (wvalid > 64) wvalid = 64;
                size_t ao = (size_t)row0 * H_;
                const float* Wh = head ? Whr : Whw;
                const float* bp = head ? bhr : bhw;
                float* dst = head ? g_Pr : g_Pw;
                tile_gemm<4, true, true, 0, 1>(sh,
                    g_hx[0] + ao, g_hx[1] + ao, g_hr[0] + ao, g_hr[1] + ao,
                    bh, H_,
                    Wh + col0, MM + 6, wvalid, bp + col0,
                    dst + (size_t)row0 * PSTR + col0, PSTR, 512);
            } else {
                int jj = j - 72;
                int row0 = (jj >> 3) * 64, col0 = (jj & 7) * 64;
                size_t ao = (size_t)row0 * H_;
                tile_gemm<4, true, true, 2, 0>(sh,
                    g_hx[0] + ao, g_hx[1] + ao, g_hr[0] + ao, g_hr[1] + ao,
                    bh, H_,
                    Wo + col0, OO, 64, bo + col0,
                    out + (size_t)row0 * (T_ * OO) + (size_t)t * OO + col0,
                    T_ * OO, 512);
            }
        }
        gbar(sense);

        // ---- P5: scores, 2 heads x ksplit2 x 64 tiles = 256 jobs ----
        for (int j = bid; j < 256; j += NB) {
            int z = j >> 7, jj = j & 127;
            int ks = jj >> 6, j2 = jj & 63;
            int row0 = (j2 >> 4) * 64, n0 = (j2 & 15) * 64;
            const float* P = (z ? g_Pr : g_Pw) + (size_t)row0 * PSTR + ks * 256;
            float* Cd = z ? (ks ? g_Cr1 : g_Cr0) : (ks ? g_Cw1 : g_Cw0);
            tile_gemm<1, true, false, 0, 2>(sh,
                P, nullptr, nullptr, nullptr, nullptr, PSTR,
                g_mem + (size_t)n0 * MM + ks * 256, MM, 64, nullptr,
                Cd + (size_t)row0 * NN + n0, NN, 256);
        }
        gbar(sense);

        // ---- P6: EA(next) 128 + addressing 512 ----
        for (int j = bid; j < 640; j += NB) {
            if (j < 128) {
                int ks = j >> 6, j2 = j & 63;
                int row0 = (j2 >> 4) * 64, col0 = (j2 & 15) * 64;
                size_t ao = (size_t)row0 * H_ + ks * 256;
                tile_gemm<4, true, true, 0, 0>(sh,
                    g_hx[0] + ao, g_hx[1] + ao, g_hr[0] + ao, g_hr[1] + ao,
                    bh + ks * 256, H_,
                    Wea + (size_t)(ks * 256) * (2 * MM) + col0, 2 * MM, 64, nullptr,
                    (ks ? g_EA1 : g_EA0) + (size_t)row0 * (2 * MM) + col0,
                    2 * MM, 256);
            } else {
                int a = j - 128;
                addr_job(sh, a & 255, a >> 8);
            }
        }
        gbar(sense);
    }
    gbar(sense);   // total: 1 + 6*128 + 1 = 770 (even)
}

extern "C" void kernel_launch(void* const* d_in, const int* in_sizes, int n_in,
                              void* d_out, int out_size)
{
    (void)in_sizes; (void)n_in; (void)out_size;
    ntm_mega<<<NB, NT>>>(
        (const float*)d_in[0],  (const float*)d_in[1],  (const float*)d_in[2],
        (const float*)d_in[3],  (const float*)d_in[4],  (const float*)d_in[5],
        (const float*)d_in[6],  (const float*)d_in[7],  (const float*)d_in[8],
        (const float*)d_in[9],  (const float*)d_in[10], (const float*)d_in[11],
        (const float*)d_in[12], (const float*)d_in[13], (const float*)d_in[14],
        (const float*)d_in[15], (float*)d_out);
}

// round 5
// speedup vs baseline: 1.4530x; 1.0168x over previous
#include <cuda_runtime.h>
#include <math.h>

#define B_   256
#define T_   128
#define I_   512
#define H_   512
#define NN   1024
#define MM   512
#define OO   512
#define PW_  518          // M+6
#define PSTR 520
#define EPS  1e-8f
#define NB   144
#define NT   512

// ---------------- persistent device state ----------------
__device__ __align__(256) float g_mem[NN * MM];
__device__ __align__(256) float g_wr[B_ * NN];
__device__ __align__(256) float g_ww[B_ * NN];
__device__ __align__(256) float g_EA[B_ * 2 * MM];    // pre-act EA accum (seed bea)
__device__ __align__(256) float g_r[B_ * MM];         // r accum (seed 0)
__device__ __align__(256) float g_hpre[B_ * H_];      // h pre-act accum (seed bh)
__device__ __align__(256) float g_Pw[B_ * PSTR];      // head pre-act (seed bias)
__device__ __align__(256) float g_Pr[B_ * PSTR];
__device__ __align__(256) float g_Cw[B_ * NN];        // scores accum (seed 0)
__device__ __align__(256) float g_Cr[B_ * NN];
__device__ __align__(256) float g_opre[B_ * OO];      // out pre-act (seed bo)
__device__ __align__(256) float g_memnorm[NN];
__device__ unsigned g_cnt;
__device__ volatile unsigned g_sense;

// ---------------- helpers ----------------
__device__ __forceinline__ float sigmoidf_(float x) { return 1.f / (1.f + expf(-x)); }
__device__ __forceinline__ float softplusf_(float x) {
    return fmaxf(x, 0.f) + log1pf(expf(-fabsf(x)));
}
__device__ __forceinline__ float warpSum(float v) {
    #pragma unroll
    for (int o = 16; o; o >>= 1) v += __shfl_xor_sync(0xffffffffu, v, o);
    return v;
}
__device__ __forceinline__ float warpMax(float v) {
    #pragma unroll
    for (int o = 16; o; o >>= 1) v = fmaxf(v, __shfl_xor_sync(0xffffffffu, v, o));
    return v;
}
__device__ float blockSum(float v, float* red) {
    int lane = threadIdx.x & 31, w = threadIdx.x >> 5;
    v = warpSum(v);
    if (lane == 0) red[w] = v;
    __syncthreads();
    if (threadIdx.x == 0) {
        float s = 0.f;
        #pragma unroll
        for (int i = 0; i < 16; i++) s += red[i];
        red[16] = s;
    }
    __syncthreads();
    float r = red[16];
    __syncthreads();
    return r;
}
__device__ float blockMax(float v, float* red) {
    int lane = threadIdx.x & 31, w = threadIdx.x >> 5;
    v = warpMax(v);
    if (lane == 0) red[w] = v;
    __syncthreads();
    if (threadIdx.x == 0) {
        float m = red[0];
        #pragma unroll
        for (int i = 1; i < 16; i++) m = fmaxf(m, red[i]);
        red[16] = m;
    }
    __syncthreads();
    float r = red[16];
    __syncthreads();
    return r;
}

__device__ __forceinline__ void gbar(unsigned& sense) {
    __threadfence();
    __syncthreads();
    if (threadIdx.x == 0) {
        unsigned ns = sense ^ 1u;
        if (atomicAdd(&g_cnt, 1u) == NB - 1u) {
            atomicExch(&g_cnt, 0u);
            __threadfence();
            g_sense = ns;
        } else {
            while (g_sense != ns) __nanosleep(32);
        }
        sense = ns;
        __threadfence();
    }
    __syncthreads();
}

// ---------------- 128x64 GEMM tile, acc 4x4, double-buffered ----------------
// A: 128 x K (row stride lda), optional elementwise tanh. One source only.
// BMODE 0: W row-major (K x wld), full 64-col tile.
// BMODE 1: W row-major with column guard (wvalid cols valid).
// BMODE 2: B[k][c] = W[c*wld + k] (transposed source, e.g. mem rows as cols).
// EPI 0: plain store; 1: atomicAdd into C. All pointers pre-offset.
template<bool ATANH, int BMODE, int EPI>
__device__ void tile_gemm2(
    float* sh,
    const float* __restrict__ A, int lda,
    const float* __restrict__ W, int wld, int wvalid,
    float* __restrict__ C, int ldc, int K)
{
    float* As = sh;          // [2][16*132]
    float* Bs = sh + 4224;   // [2][16*68]
    const int tid = threadIdx.x;
    const int aR = tid >> 2, aK = (tid & 3) * 4;
    const int bK = tid >> 5, bC = (tid & 31) * 2;
    const int b2n = tid & 63, b2k = (tid >> 6) * 2;
    const int ty = tid >> 4, tx = tid & 15;
    float ar[4], bw[2];

    auto loadA = [&](int k0) {
        float4 v = *(const float4*)(A + (size_t)aR * lda + k0 + aK);
        if (ATANH) {
            v.x = tanhf(v.x); v.y = tanhf(v.y);
            v.z = tanhf(v.z); v.w = tanhf(v.w);
        }
        ar[0] = v.x; ar[1] = v.y; ar[2] = v.z; ar[3] = v.w;
    };
    auto loadB = [&](int k0) {
        if (BMODE == 0) {
            float2 v = *(const float2*)(W + (size_t)(k0 + bK) * wld + bC);
            bw[0] = v.x; bw[1] = v.y;
        } else if (BMODE == 1) {
            bw[0] = (bC     < wvalid) ? W[(size_t)(k0 + bK) * wld + bC]     : 0.f;
            bw[1] = (bC + 1 < wvalid) ? W[(size_t)(k0 + bK) * wld + bC + 1] : 0.f;
        } else {
            float2 v = *(const float2*)(W + (size_t)b2n * wld + k0 + b2k);
            bw[0] = v.x; bw[1] = v.y;
        }
    };
    auto storeAB = [&](int buf) {
        float* Ab = As + buf * 2112;
        #pragma unroll
        for (int u = 0; u < 4; u++) Ab[(aK + u) * 132 + aR] = ar[u];
        float* Bb = Bs + buf * 1088;
        if (BMODE == 2) {
            Bb[b2k * 68 + b2n] = bw[0];
            Bb[(b2k + 1) * 68 + b2n] = bw[1];
        } else {
            *(float2*)&Bb[bK * 68 + bC] = make_float2(bw[0], bw[1]);
        }
    };

    float acc[4][4] = {};
    loadA(0); loadB(0); storeAB(0);
    __syncthreads();
    int buf = 0;
    for (int k0 = 0; k0 < K; k0 += 16) {
        bool more = (k0 + 16) < K;
        if (more) { loadA(k0 + 16); loadB(k0 + 16); }
        float* Ab = As + buf * 2112;
        float* Bb = Bs + buf * 1088;
        #pragma unroll
        for (int kk = 0; kk < 16; kk++) {
            float4 a4 = *(const float4*)&Ab[kk * 132 + ty * 4];
            float4 b4 = *(const float4*)&Bb[kk * 68 + tx * 4];
            float av[4] = {a4.x, a4.y, a4.z, a4.w};
            float bv[4] = {b4.x, b4.y, b4.z, b4.w};
            #pragma unroll
            for (int i = 0; i < 4; i++)
                #pragma unroll
                for (int j = 0; j < 4; j++)
                    acc[i][j] = fmaf(av[i], bv[j], acc[i][j]);
        }
        if (more) storeAB(buf ^ 1);
        __syncthreads();
        buf ^= 1;
    }
    #pragma unroll
    for (int j = 0; j < 4; j++) {
        int c = tx * 4 + j;
        if (BMODE == 1 && c >= wvalid) continue;
        #pragma unroll
        for (int i = 0; i < 4; i++) {
            float* p = C + (size_t)(ty * 4 + i) * ldc + c;
            if (EPI == 1) atomicAdd(p, acc[i][j]);
            else *p = acc[i][j];
        }
    }
}

// ---------------- memory update tile 64n x 64m (dual acc, K = B = 256) ----
__device__ void tile_memupd(float* sh, int n0, int m0)
{
    float* Ws  = sh;            // [2][32][68]
    float* Es  = sh + 4352;
    float* Aas = sh + 8704;
    const int tid = threadIdx.x;
    const int wK = tid >> 4, wC = (tid & 15) * 4;
    const int ty = tid >> 5, tx = tid & 31;
    float wr_[4], ev[4], av[4];

    auto loadAll = [&](int b0) {
        float4 w = *(const float4*)(g_ww + (size_t)(b0 + wK) * NN + n0 + wC);
        wr_[0] = w.x; wr_[1] = w.y; wr_[2] = w.z; wr_[3] = w.w;
        size_t ro = (size_t)(b0 + wK) * (2 * MM);
        float4 e0 = *(const float4*)(g_EA + ro + m0 + wC);
        float4 a0 = *(const float4*)(g_EA + ro + MM + m0 + wC);
        ev[0] = sigmoidf_(e0.x); ev[1] = sigmoidf_(e0.y);
        ev[2] = sigmoidf_(e0.z); ev[3] = sigmoidf_(e0.w);
        av[0] = tanhf(a0.x); av[1] = tanhf(a0.y);
        av[2] = tanhf(a0.z); av[3] = tanhf(a0.w);
    };
    auto storeAll = [&](int buf) {
        *(float4*)&Ws [buf * 2176 + wK * 68 + wC] = make_float4(wr_[0], wr_[1], wr_[2], wr_[3]);
        *(float4*)&Es [buf * 2176 + wK * 68 + wC] = make_float4(ev[0], ev[1], ev[2], ev[3]);
        *(float4*)&Aas[buf * 2176 + wK * 68 + wC] = make_float4(av[0], av[1], av[2], av[3]);
    };

    float ae[4][2] = {}, aa[4][2] = {};
    loadAll(0); storeAll(0);
    __syncthreads();
    int buf = 0;
    for (int b0 = 0; b0 < B_; b0 += 32) {
        bool more = (b0 + 32) < B_;
        if (more) loadAll(b0 + 32);
        float* Wb = Ws + buf * 2176;
        float* Eb = Es + buf * 2176;
        float* Ab = Aas + buf * 2176;
        #pragma unroll
        for (int kk = 0; kk < 32; kk++) {
            float4 w4 = *(const float4*)&Wb[kk * 68 + ty * 4];
            float2 e2 = *(const float2*)&Eb[kk * 68 + tx * 2];
            float2 a2 = *(const float2*)&Ab[kk * 68 + tx * 2];
            float wv[4] = {w4.x, w4.y, w4.z, w4.w};
            #pragma unroll
            for (int i = 0; i < 4; i++) {
                ae[i][0] = fmaf(wv[i], e2.x, ae[i][0]);
                ae[i][1] = fmaf(wv[i], e2.y, ae[i][1]);
                aa[i][0] = fmaf(wv[i], a2.x, aa[i][0]);
                aa[i][1] = fmaf(wv[i], a2.y, aa[i][1]);
            }
        }
        if (more) storeAll(buf ^ 1);
        __syncthreads();
        buf ^= 1;
    }
    const float invB = 1.f / (float)B_;
    #pragma unroll
    for (int i = 0; i < 4; i++)
        #pragma unroll
        for (int j = 0; j < 2; j++) {
            size_t idx = (size_t)(n0 + ty * 4 + i) * MM + m0 + tx * 2 + j;
            float mo = g_mem[idx];
            g_mem[idx] = mo * (1.f - ae[i][j] * invB) + aa[i][j] * invB;
        }
}

// ---------------- per-row memory norms (64 rows per job) ----------------
__device__ void norm_job(int nj) {
    const int t = threadIdx.x;
    const int row = nj * 64 + (t >> 3);
    const int p = t & 7;
    const float* rp = g_mem + (size_t)row * MM;
    float s = 0.f;
    #pragma unroll
    for (int u = 0; u < 64; u++) {
        float v = rp[p + u * 8];
        s += v * v;
    }
    s += __shfl_xor_sync(0xffffffffu, s, 1);
    s += __shfl_xor_sync(0xffffffffu, s, 2);
    s += __shfl_xor_sync(0xffffffffu, s, 4);
    if (p == 0) g_memnorm[row] = sqrtf(s);
}

// ---------------- addressing (batch row b, head z), 512 threads ----------
__device__ void addr_job(float* sh, int b, int z) {
    float* swg  = sh;            // 1024
    float* red  = sh + 1024;     // 17
    float* scal = sh + 1044;     // 7
    const float* P = (z ? g_Pr : g_Pw) + (size_t)b * PSTR;
    const float* C = (z ? g_Cr : g_Cw) + (size_t)b * NN;
    float* wrow = (z ? g_wr : g_ww) + (size_t)b * NN;
    const int tid = threadIdx.x;
    __syncthreads();

    float kx = tanhf(P[tid]);                 // MM == NT
    float s = blockSum(kx * kx, red);
    if (tid == 0) {
        scal[6] = sqrtf(s) + EPS;
        float p0 = P[MM], p1 = P[MM + 1], p2 = P[MM + 2];
        float p3 = P[MM + 3], p4 = P[MM + 4], p5 = P[MM + 5];
        scal[0] = softplusf_(p0);
        scal[1] = sigmoidf_(p1);
        float m = fmaxf(p2, fmaxf(p3, p4));
        float e0 = expf(p2 - m), e1 = expf(p3 - m), e2 = expf(p4 - m);
        float ss = e0 + e1 + e2;
        scal[2] = e0 / ss; scal[3] = e1 / ss; scal[4] = e2 / ss;
        scal[5] = 1.f + softplusf_(p5);
    }
    __syncthreads();
    float beta = scal[0], gg = scal[1], s0 = scal[2], s1 = scal[3], s2 = scal[4];
    float gamma = scal[5], knorm = scal[6];

    float v[2];
    float mx = -3.4e38f;
    #pragma unroll
    for (int u = 0; u < 2; u++) {
        int n = tid + u * NT;
        float sc = beta * C[n] / (knorm * (g_memnorm[n] + EPS));
        v[u] = sc;
        mx = fmaxf(mx, sc);
    }
    mx = blockMax(mx, red);
    float se = 0.f;
    #pragma unroll
    for (int u = 0; u < 2; u++) {
        v[u] = expf(v[u] - mx);
        se += v[u];
    }
    se = blockSum(se, red);
    float inv = 1.f / se;
    #pragma unroll
    for (int u = 0; u < 2; u++) {
        int n = tid + u * NT;
        swg[n] = gg * v[u] * inv + (1.f - gg) * wrow[n];
    }
    __syncthreads();
    float S = 0.f;
    #pragma unroll
    for (int u = 0; u < 2; u++) {
        int n = tid + u * NT;
        float wt = s1 * swg[n] + s0 * swg[(n + 1) & (NN - 1)] + s2 * swg[(n - 1) & (NN - 1)];
        v[u] = powf(wt, gamma);
        S += v[u];
    }
    S = blockSum(S, red);
    float invS = 1.f / (S + EPS);
    #pragma unroll
    for (int u = 0; u < 2; u++)
        wrow[tid + u * NT] = v[u] * invS;
    __syncthreads();
}

// ---------------- seed helpers (one job = 1/PARTS of buffer) ----------------
__device__ void seed_bcast(float* dst, const float* src, int width, int total,
                           int part, int parts) {
    int per = total / parts;
    int base = part * per;
    for (int i = threadIdx.x; i < per; i += NT) {
        int idx = base + i;
        dst[idx] = src[idx % width];
    }
}
__device__ void seed_zero(float* dst, int total, int part, int parts) {
    int per4 = total / (4 * parts);
    float4* d = (float4*)dst + part * per4;
    float4 z = make_float4(0.f, 0.f, 0.f, 0.f);
    for (int i = threadIdx.x; i < per4; i += NT) d[i] = z;
}
__device__ void seed_pbias(float* dst, const float* bias, int part, int parts) {
    int per = B_ * PSTR / parts;
    int base = part * per;
    for (int i = threadIdx.x; i < per; i += NT) {
        int idx = base + i;
        int c = idx % PSTR;
        dst[idx] = (c < PW_) ? bias[c] : 0.f;
    }
}

// ---------------- the megakernel ----------------
__global__ void __launch_bounds__(NT, 1) ntm_mega(
    const float* __restrict__ x,
    const float* __restrict__ mem0, const float* __restrict__ wr0,
    const float* __restrict__ ww0, const float* __restrict__ h0,
    const float* __restrict__ Wx, const float* __restrict__ Wr,
    const float* __restrict__ bh,
    const float* __restrict__ Whr, const float* __restrict__ bhr,
    const float* __restrict__ Whw, const float* __restrict__ bhw,
    const float* __restrict__ Wea, const float* __restrict__ bea,
    const float* __restrict__ Wo, const float* __restrict__ bo,
    float* __restrict__ out)
{
    __shared__ float sh[13120];
    unsigned sense = 0;
    const int bid = blockIdx.x;
    const int tid = threadIdx.x;
    const int gthread = bid * NT + tid;

    // INIT-A: copy state; seed EA with bea
    for (int i = gthread; i < NN * MM; i += NB * NT) g_mem[i] = mem0[i];
    for (int i = gthread; i < B_ * NN; i += NB * NT) {
        g_wr[i] = wr0[i];
        g_ww[i] = ww0[i];
    }
    for (int j = bid; j < 4; j += NB)
        seed_bcast(g_EA, bea, 2 * MM, B_ * 2 * MM, j, 4);
    gbar(sense);                                             // 1

    // INIT-B: EA(0) += h0 @ Wea   (ksplit4, K=128, 2x16x4 = 128 jobs)
    for (int j = bid; j < 128; j += NB) {
        int ks = j & 3, rest = j >> 2;
        int row0 = (rest & 1) * 128, col0 = (rest >> 1) * 64;
        tile_gemm2<false, 0, 1>(sh,
            h0 + (size_t)row0 * H_ + ks * 128, H_,
            Wea + (size_t)(ks * 128) * (2 * MM) + col0, 2 * MM, 64,
            g_EA + (size_t)row0 * (2 * MM) + col0, 2 * MM, 128);
    }
    gbar(sense);                                             // 2

    for (int t = 0; t < T_; t++) {
        // ---- P1: memupd(128) + seed r(2)/hpre(2)/Pw(2)/Pr(2) = 136 ----
        for (int j = bid; j < 136; j += NB) {
            if (j < 128) {
                tile_memupd(sh, (j >> 3) * 64, (j & 7) * 64);
            } else if (j < 130) {
                seed_zero(g_r, B_ * MM, j - 128, 2);
            } else if (j < 132) {
                seed_bcast(g_hpre, bh, H_, B_ * H_, j - 130, 2);
            } else if (j < 134) {
                seed_pbias(g_Pw, bhw, j - 132, 2);
            } else {
                seed_pbias(g_Pr, bhr, j - 134, 2);
            }
        }
        gbar(sense);

        // ---- P2: r(64, K=256) + hx(32, K=256) + norms(16) + seedC(8) = 120 --
        for (int j = bid; j < 120; j += NB) {
            if (j < 64) {
                int ks = j & 3, rest = j >> 2;
                int row0 = (rest & 1) * 128, col0 = (rest >> 1) * 64;
                tile_gemm2<false, 0, 1>(sh,
                    g_wr + (size_t)row0 * NN + ks * 256, NN,
                    g_mem + (size_t)(ks * 256) * MM + col0, MM, 64,
                    g_r + (size_t)row0 * MM + col0, MM, 256);
            } else if (j < 96) {
                int jj = j - 64;
                int ks = jj & 1, rest = jj >> 1;
                int row0 = (rest & 1) * 128, col0 = (rest >> 1) * 64;
                tile_gemm2<false, 0, 1>(sh,
                    x + (size_t)row0 * (T_ * I_) + (size_t)t * I_ + ks * 256, T_ * I_,
                    Wx + (size_t)(ks * 256) * H_ + col0, H_, 64,
                    g_hpre + (size_t)row0 * H_ + col0, H_, 256);
            } else if (j < 112) {
                norm_job(j - 96);
            } else {
                int jj = j - 112;   // 0..7 zero Cw/Cr
                if (jj < 4) seed_zero(g_Cw, B_ * NN, jj, 4);
                else        seed_zero(g_Cr, B_ * NN, jj - 4, 4);
            }
        }
        gbar(sense);

        // ---- P3: hr(64, K=128) + seedEA(4) + seedOpre(2) = 70 ----
        for (int j = bid; j < 70; j += NB) {
            if (j < 64) {
                int ks = j & 3, rest = j >> 2;
                int row0 = (rest & 1) * 128, col0 = (rest >> 1) * 64;
                tile_gemm2<false, 0, 1>(sh,
                    g_r + (size_t)row0 * MM + ks * 128, MM,
                    Wr + (size_t)(ks * 128) * H_ + col0, H_, 64,
                    g_hpre + (size_t)row0 * H_ + col0, H_, 128);
            } else if (j < 68) {
                seed_bcast(g_EA, bea, 2 * MM, B_ * 2 * MM, j - 64, 4);
            } else {
                seed_bcast(g_opre, bo, OO, B_ * OO, j - 68, 2);
            }
        }
        gbar(sense);

        // ---- P4: Pw(36) + Pr(36) + out(32) = 104, K=256, A = tanh(hpre) ----
        for (int j = bid; j < 104; j += NB) {
            if (j < 72) {
                int head = j / 36, jj = j % 36;
                int ks = jj & 1, rest = jj >> 1;      // rest 0..17
                int row0 = (rest & 1) * 128, ct = rest >> 1;   // ct 0..8
                int col0 = ct * 64;
                int wv = PW_ - col0; if (wv > 64) wv = 64;
                const float* Wh = head ? Whr : Whw;
                float* dst = head ? g_Pr : g_Pw;
                tile_gemm2<true, 1, 1>(sh,
                    g_hpre + (size_t)row0 * H_ + ks * 256, H_,
                    Wh + (size_t)(ks * 256) * PW_ + col0, PW_, wv,
                    dst + (size_t)row0 * PSTR + col0, PSTR, 256);
            } else {
                int jj = j - 72;
                int ks = jj & 1, rest = jj >> 1;
                int row0 = (rest & 1) * 128, col0 = (rest >> 1) * 64;
                tile_gemm2<true, 0, 1>(sh,
                    g_hpre + (size_t)row0 * H_ + ks * 256, H_,
                    Wo + (size_t)(ks * 256) * OO + col0, OO, 64,
                    g_opre + (size_t)row0 * OO + col0, OO, 256);
            }
        }
        gbar(sense);

        // ---- P5: scores 128 jobs (2 heads x 2 rows x 16 ncols x ks2, K=256) --
        for (int j = bid; j < 128; j += NB) {
            int z = j >> 6, jj = j & 63;
            int ks = jj & 1, rest = jj >> 1;
            int row0 = (rest & 1) * 128, n0 = (rest >> 1) * 64;
            const float* P = (z ? g_Pr : g_Pw) + (size_t)row0 * PSTR + ks * 256;
            float* Cd = (z ? g_Cr : g_Cw) + (size_t)row0 * NN + n0;
            tile_gemm2<true, 2, 1>(sh,
                P, PSTR,
                g_mem + (size_t)n0 * MM + ks * 256, MM, 64,
                Cd, NN, 256);
        }
        gbar(sense);

        // ---- P6: addr(512) + outfin(8) + EA(128, K=128) = 648 ----
        for (int j = bid; j < 648; j += NB) {
            if (j < 512) {
                addr_job(sh, j & 255, j >> 8);
            } else if (j < 520) {
                int jj = j - 512;
                for (int l = tid; l < 16384; l += NT) {
                    int e = jj * 16384 + l;
                    int b = e >> 9, o = e & 511;
                    out[((size_t)b * T_ + t) * OO + o] = sigmoidf_(g_opre[e]);
                }
            } else {
                int jj = j - 520;
                int ks = jj & 3, rest = jj >> 2;
                int row0 = (rest & 1) * 128, col0 = (rest >> 1) * 64;
                tile_gemm2<true, 0, 1>(sh,
                    g_hpre + (size_t)row0 * H_ + ks * 128, H_,
                    Wea + (size_t)(ks * 128) * (2 * MM) + col0, 2 * MM, 64,
                    g_EA + (size_t)row0 * (2 * MM) + col0, 2 * MM, 128);
            }
        }
        gbar(sense);
    }
    // total barriers: 2 + 6*128 = 770 (even)
}

extern "C" void kernel_launch(void* const* d_in, const int* in_sizes, int n_in,
                              void* d_out, int out_size)
{
    (void)in_sizes; (void)n_in; (void)out_size;
    ntm_mega<<<NB, NT>>>(
        (const float*)d_in[0],  (const float*)d_in[1],  (const float*)d_in[2],
        (const float*)d_in[3],  (const float*)d_in[4],  (const float*)d_in[5],
        (const float*)d_in[6],  (const float*)d_in[7],  (const float*)d_in[8],
        (const float*)d_in[9],  (const float*)d_in[10], (const float*)d_in[11],
        (const float*)d_in[12], (const float*)d_in[13], (const float*)d_in[14],
        (const float*)d_in[15], (float*)d_out);
}

// round 6
// speedup vs baseline: 1.4744x; 1.0147x over previous
#include <cuda_runtime.h>
#include <math.h>

#define B_   256
#define T_   128
#define I_   512
#define H_   512
#define NN   1024
#define MM   512
#define OO   512
#define PW_  518          // M+6
#define PSTR 520
#define EPS  1e-8f
#define NB   144
#define NT   512

// ---------------- persistent device state ----------------
__device__ __align__(256) float g_mem[NN * MM];
__device__ __align__(256) float g_wr[B_ * NN];
__device__ __align__(256) float g_ww[B_ * NN];
__device__ __align__(256) float g_EA[B_ * 2 * MM];    // pre-act EA accum (seed bea)
__device__ __align__(256) float g_r[B_ * MM];         // r accum (seed 0)
__device__ __align__(256) float g_hpre[B_ * H_];      // h pre-act accum (seed bh)
__device__ __align__(256) float g_Pw[B_ * PSTR];      // head pre-act (seed bias)
__device__ __align__(256) float g_Pr[B_ * PSTR];
__device__ __align__(256) float g_Cw[B_ * NN];        // scores accum (seed 0)
__device__ __align__(256) float g_Cr[B_ * NN];
__device__ __align__(256) float g_opre[B_ * OO];      // out pre-act (seed bo)
__device__ __align__(256) float g_memnorm[NN];
__device__ unsigned g_cnt;
__device__ volatile unsigned g_sense;

// ---------------- scalar helpers ----------------
__device__ __forceinline__ float sigmoidf_(float x) { return 1.f / (1.f + expf(-x)); }
__device__ __forceinline__ float softplusf_(float x) {
    return fmaxf(x, 0.f) + log1pf(expf(-fabsf(x)));
}
__device__ __forceinline__ float warpSum(float v) {
    #pragma unroll
    for (int o = 16; o; o >>= 1) v += __shfl_xor_sync(0xffffffffu, v, o);
    return v;
}
__device__ __forceinline__ float warpMax(float v) {
    #pragma unroll
    for (int o = 16; o; o >>= 1) v = fmaxf(v, __shfl_xor_sync(0xffffffffu, v, o));
    return v;
}

// ---------------- packed f32x2 helpers (Blackwell FFMA2) ----------------
__device__ __forceinline__ unsigned long long pack2(float a, float b) {
    unsigned long long r;
    asm("mov.b64 %0, {%1, %2};" : "=l"(r) : "f"(a), "f"(b));
    return r;
}
__device__ __forceinline__ void fma2(unsigned long long& d,
                                     unsigned long long a, unsigned long long b) {
    asm("fma.rn.f32x2 %0, %1, %2, %0;" : "+l"(d) : "l"(a), "l"(b));
}
__device__ __forceinline__ float2 unpack2(unsigned long long v) {
    float2 r;
    asm("mov.b64 {%0, %1}, %2;" : "=f"(r.x), "=f"(r.y) : "l"(v));
    return r;
}

// ---------------- grid barrier ----------------
__device__ __forceinline__ void gbar(unsigned& sense) {
    __threadfence();
    __syncthreads();
    if (threadIdx.x == 0) {
        unsigned ns = sense ^ 1u;
        if (atomicAdd(&g_cnt, 1u) == NB - 1u) {
            atomicExch(&g_cnt, 0u);
            __threadfence();
            g_sense = ns;
        } else {
            while (g_sense != ns) __nanosleep(32);
        }
        sense = ns;
        __threadfence();
    }
    __syncthreads();
}

// ---------------- 256-thread group barrier / reductions ----------------
__device__ __forceinline__ void barx(int id) {
    asm volatile("bar.sync %0, 256;" :: "r"(id) : "memory");
}
__device__ float grpSum(float v, float* red, int id) {
    int t = threadIdx.x & 255;
    int lane = t & 31, w = t >> 5;
    v = warpSum(v);
    if (lane == 0) red[w] = v;
    barx(id);
    float s = 0.f;
    #pragma unroll
    for (int i = 0; i < 8; i++) s += red[i];
    barx(id);
    return s;
}
__device__ float grpMax(float v, float* red, int id) {
    int t = threadIdx.x & 255;
    int lane = t & 31, w = t >> 5;
    v = warpMax(v);
    if (lane == 0) red[w] = v;
    barx(id);
    float m = red[0];
    #pragma unroll
    for (int i = 1; i < 8; i++) m = fmaxf(m, red[i]);
    barx(id);
    return m;
}

// ---------------- 128x64 GEMM tile, packed acc 4x(2x2), double-buffered ----
// BMODE 0: W row-major full tile; 1: row-major + col guard; 2: transposed src.
// EPI 1: atomicAdd into C. ATANH: tanh on A elements.
template<bool ATANH, int BMODE, int EPI>
__device__ void tile_gemm2(
    float* sh,
    const float* __restrict__ A, int lda,
    const float* __restrict__ W, int wld, int wvalid,
    float* __restrict__ C, int ldc, int K)
{
    float* As = sh;          // [2][16*132]
    float* Bs = sh + 4224;   // [2][16*68]
    const int tid = threadIdx.x;
    const int aR = tid >> 2, aK = (tid & 3) * 4;
    const int bK = tid >> 5, bC = (tid & 31) * 2;
    const int b2n = tid & 63, b2k = (tid >> 6) * 2;
    const int ty = tid >> 4, tx = tid & 15;
    float ar[4], bw[2];

    auto loadA = [&](int k0) {
        float4 v = *(const float4*)(A + (size_t)aR * lda + k0 + aK);
        if (ATANH) {
            v.x = tanhf(v.x); v.y = tanhf(v.y);
            v.z = tanhf(v.z); v.w = tanhf(v.w);
        }
        ar[0] = v.x; ar[1] = v.y; ar[2] = v.z; ar[3] = v.w;
    };
    auto loadB = [&](int k0) {
        if (BMODE == 0) {
            float2 v = *(const float2*)(W + (size_t)(k0 + bK) * wld + bC);
            bw[0] = v.x; bw[1] = v.y;
        } else if (BMODE == 1) {
            bw[0] = (bC     < wvalid) ? W[(size_t)(k0 + bK) * wld + bC]     : 0.f;
            bw[1] = (bC + 1 < wvalid) ? W[(size_t)(k0 + bK) * wld + bC + 1] : 0.f;
        } else {
            float2 v = *(const float2*)(W + (size_t)b2n * wld + k0 + b2k);
            bw[0] = v.x; bw[1] = v.y;
        }
    };
    auto storeAB = [&](int buf) {
        float* Ab = As + buf * 2112;
        #pragma unroll
        for (int u = 0; u < 4; u++) Ab[(aK + u) * 132 + aR] = ar[u];
        float* Bb = Bs + buf * 1088;
        if (BMODE == 2) {
            Bb[b2k * 68 + b2n] = bw[0];
            Bb[(b2k + 1) * 68 + b2n] = bw[1];
        } else {
            *(float2*)&Bb[bK * 68 + bC] = make_float2(bw[0], bw[1]);
        }
    };

    unsigned long long acc2[4][2] = {};
    loadA(0); loadB(0); storeAB(0);
    __syncthreads();
    int buf = 0;
    for (int k0 = 0; k0 < K; k0 += 16) {
        bool more = (k0 + 16) < K;
        if (more) { loadA(k0 + 16); loadB(k0 + 16); }
        float* Ab = As + buf * 2112;
        float* Bb = Bs + buf * 1088;
        #pragma unroll
        for (int kk = 0; kk < 16; kk++) {
            float4 a4 = *(const float4*)&Ab[kk * 132 + ty * 4];
            ulonglong2 bp = *(const ulonglong2*)&Bb[kk * 68 + tx * 4];
            unsigned long long av;
            av = pack2(a4.x, a4.x); fma2(acc2[0][0], av, bp.x); fma2(acc2[0][1], av, bp.y);
            av = pack2(a4.y, a4.y); fma2(acc2[1][0], av, bp.x); fma2(acc2[1][1], av, bp.y);
            av = pack2(a4.z, a4.z); fma2(acc2[2][0], av, bp.x); fma2(acc2[2][1], av, bp.y);
            av = pack2(a4.w, a4.w); fma2(acc2[3][0], av, bp.x); fma2(acc2[3][1], av, bp.y);
        }
        if (more) storeAB(buf ^ 1);
        __syncthreads();
        buf ^= 1;
    }
    #pragma unroll
    for (int i = 0; i < 4; i++) {
        #pragma unroll
        for (int jp = 0; jp < 2; jp++) {
            float2 v = unpack2(acc2[i][jp]);
            int c0 = tx * 4 + jp * 2;
            float* rowp = C + (size_t)(ty * 4 + i) * ldc;
            if (BMODE != 1 || c0 < wvalid) {
                if (EPI == 1) atomicAdd(rowp + c0, v.x); else rowp[c0] = v.x;
            }
            if (BMODE != 1 || c0 + 1 < wvalid) {
                if (EPI == 1) atomicAdd(rowp + c0 + 1, v.y); else rowp[c0 + 1] = v.y;
            }
        }
    }
}

// ---------------- memory update tile 64n x 64m (dual packed acc, K=256) ----
__device__ void tile_memupd(float* sh, int n0, int m0)
{
    float* Ws  = sh;            // [2][32][68]
    float* Es  = sh + 4352;
    float* Aas = sh + 8704;
    const int tid = threadIdx.x;
    const int wK = tid >> 4, wC = (tid & 15) * 4;
    const int ty = tid >> 5, tx = tid & 31;
    float wr_[4], ev[4], av[4];

    auto loadAll = [&](int b0) {
        float4 w = *(const float4*)(g_ww + (size_t)(b0 + wK) * NN + n0 + wC);
        wr_[0] = w.x; wr_[1] = w.y; wr_[2] = w.z; wr_[3] = w.w;
        size_t ro = (size_t)(b0 + wK) * (2 * MM);
        float4 e0 = *(const float4*)(g_EA + ro + m0 + wC);
        float4 a0 = *(const float4*)(g_EA + ro + MM + m0 + wC);
        ev[0] = sigmoidf_(e0.x); ev[1] = sigmoidf_(e0.y);
        ev[2] = sigmoidf_(e0.z); ev[3] = sigmoidf_(e0.w);
        av[0] = tanhf(a0.x); av[1] = tanhf(a0.y);
        av[2] = tanhf(a0.z); av[3] = tanhf(a0.w);
    };
    auto storeAll = [&](int buf) {
        *(float4*)&Ws [buf * 2176 + wK * 68 + wC] = make_float4(wr_[0], wr_[1], wr_[2], wr_[3]);
        *(float4*)&Es [buf * 2176 + wK * 68 + wC] = make_float4(ev[0], ev[1], ev[2], ev[3]);
        *(float4*)&Aas[buf * 2176 + wK * 68 + wC] = make_float4(av[0], av[1], av[2], av[3]);
    };

    unsigned long long ae2[4] = {}, aa2[4] = {};
    loadAll(0); storeAll(0);
    __syncthreads();
    int buf = 0;
    for (int b0 = 0; b0 < B_; b0 += 32) {
        bool more = (b0 + 32) < B_;
        if (more) loadAll(b0 + 32);
        float* Wb = Ws + buf * 2176;
        float* Eb = Es + buf * 2176;
        float* Ab = Aas + buf * 2176;
        #pragma unroll
        for (int kk = 0; kk < 32; kk++) {
            float4 w4 = *(const float4*)&Wb[kk * 68 + ty * 4];
            unsigned long long e2 = *(const unsigned long long*)&Eb[kk * 68 + tx * 2];
            unsigned long long a2 = *(const unsigned long long*)&Ab[kk * 68 + tx * 2];
            unsigned long long wv;
            wv = pack2(w4.x, w4.x); fma2(ae2[0], wv, e2); fma2(aa2[0], wv, a2);
            wv = pack2(w4.y, w4.y); fma2(ae2[1], wv, e2); fma2(aa2[1], wv, a2);
            wv = pack2(w4.z, w4.z); fma2(ae2[2], wv, e2); fma2(aa2[2], wv, a2);
            wv = pack2(w4.w, w4.w); fma2(ae2[3], wv, e2); fma2(aa2[3], wv, a2);
        }
        if (more) storeAll(buf ^ 1);
        __syncthreads();
        buf ^= 1;
    }
    const float invB = 1.f / (float)B_;
    #pragma unroll
    for (int i = 0; i < 4; i++) {
        float2 e = unpack2(ae2[i]);
        float2 a = unpack2(aa2[i]);
        size_t idx = (size_t)(n0 + ty * 4 + i) * MM + m0 + tx * 2;
        float m0v = g_mem[idx], m1v = g_mem[idx + 1];
        g_mem[idx]     = m0v * (1.f - e.x * invB) + a.x * invB;
        g_mem[idx + 1] = m1v * (1.f - e.y * invB) + a.y * invB;
    }
}

// ---------------- per-row memory norms (64 rows per job) ----------------
__device__ void norm_job(int nj) {
    const int t = threadIdx.x;
    const int row = nj * 64 + (t >> 3);
    const int p = t & 7;
    const float* rp = g_mem + (size_t)row * MM;
    float s = 0.f;
    #pragma unroll
    for (int u = 0; u < 64; u++) {
        float v = rp[p + u * 8];
        s += v * v;
    }
    s += __shfl_xor_sync(0xffffffffu, s, 1);
    s += __shfl_xor_sync(0xffffffffu, s, 2);
    s += __shfl_xor_sync(0xffffffffu, s, 4);
    if (p == 0) g_memnorm[row] = sqrtf(s);
}

// ---------------- addressing: 2 jobs/block via 256-thread groups ----------
__device__ void addr_dual(float* sh, int idx) {
    const int g = threadIdx.x >> 8;          // group 0/1
    const int t = threadIdx.x & 255;
    const int id = 1 + g;                    // named barrier id
    float* swg  = sh + g * 1024;
    float* red  = sh + 2048 + g * 16;
    float* scal = sh + 2080 + g * 8;
    const int b = idx & 255, z = idx >> 8;
    const float* P = (z ? g_Pr : g_Pw) + (size_t)b * PSTR;
    const float* C = (z ? g_Cr : g_Cw) + (size_t)b * NN;
    float* wrow = (z ? g_wr : g_ww) + (size_t)b * NN;

    barx(id);                                // protect smem from previous job
    float k0 = tanhf(P[t]), k1 = tanhf(P[t + 256]);
    float s = grpSum(k0 * k0 + k1 * k1, red, id);
    if (t == 0) {
        scal[6] = sqrtf(s) + EPS;
        float p0 = P[MM], p1 = P[MM + 1], p2 = P[MM + 2];
        float p3 = P[MM + 3], p4 = P[MM + 4], p5 = P[MM + 5];
        scal[0] = softplusf_(p0);
        scal[1] = sigmoidf_(p1);
        float m = fmaxf(p2, fmaxf(p3, p4));
        float e0 = expf(p2 - m), e1 = expf(p3 - m), e2 = expf(p4 - m);
        float ss = e0 + e1 + e2;
        scal[2] = e0 / ss; scal[3] = e1 / ss; scal[4] = e2 / ss;
        scal[5] = 1.f + softplusf_(p5);
    }
    barx(id);
    float beta = scal[0], gg = scal[1], s0 = scal[2], s1 = scal[3], s2 = scal[4];
    float gamma = scal[5], knorm = scal[6];

    float v[4];
    float mx = -3.4e38f;
    #pragma unroll
    for (int u = 0; u < 4; u++) {
        int n = t + u * 256;
        float sc = beta * C[n] / (knorm * (g_memnorm[n] + EPS));
        v[u] = sc;
        mx = fmaxf(mx, sc);
    }
    mx = grpMax(mx, red, id);
    float se = 0.f;
    #pragma unroll
    for (int u = 0; u < 4; u++) {
        v[u] = expf(v[u] - mx);
        se += v[u];
    }
    se = grpSum(se, red, id);
    float inv = 1.f / se;
    #pragma unroll
    for (int u = 0; u < 4; u++) {
        int n = t + u * 256;
        swg[n] = gg * v[u] * inv + (1.f - gg) * wrow[n];
    }
    barx(id);
    float S = 0.f;
    #pragma unroll
    for (int u = 0; u < 4; u++) {
        int n = t + u * 256;
        float wt = s1 * swg[n] + s0 * swg[(n + 1) & (NN - 1)] + s2 * swg[(n - 1) & (NN - 1)];
        v[u] = powf(wt, gamma);
        S += v[u];
    }
    S = grpSum(S, red, id);
    float invS = 1.f / (S + EPS);
    #pragma unroll
    for (int u = 0; u < 4; u++)
        wrow[t + u * 256] = v[u] * invS;
}

// ---------------- seed helpers ----------------
__device__ void seed_bcast(float* dst, const float* src, int width, int total,
                           int part, int parts) {
    int per = total / parts;
    int base = part * per;
    for (int i = threadIdx.x; i < per; i += NT) {
        int idx = base + i;
        dst[idx] = src[idx % width];
    }
}
__device__ void seed_zero(float* dst, int total, int part, int parts) {
    int per4 = total / (4 * parts);
    float4* d = (float4*)dst + part * per4;
    float4 z = make_float4(0.f, 0.f, 0.f, 0.f);
    for (int i = threadIdx.x; i < per4; i += NT) d[i] = z;
}
__device__ void seed_pbias(float* dst, const float* bias, int part, int parts) {
    int per = B_ * PSTR / parts;
    int base = part * per;
    for (int i = threadIdx.x; i < per; i += NT) {
        int idx = base + i;
        int c = idx % PSTR;
        dst[idx] = (c < PW_) ? bias[c] : 0.f;
    }
}

// ---------------- the megakernel ----------------
__global__ void __launch_bounds__(NT, 1) ntm_mega(
    const float* __restrict__ x,
    const float* __restrict__ mem0, const float* __restrict__ wr0,
    const float* __restrict__ ww0, const float* __restrict__ h0,
    const float* __restrict__ Wx, const float* __restrict__ Wr,
    const float* __restrict__ bh,
    const float* __restrict__ Whr, const float* __restrict__ bhr,
    const float* __restrict__ Whw, const float* __restrict__ bhw,
    const float* __restrict__ Wea, const float* __restrict__ bea,
    const float* __restrict__ Wo, const float* __restrict__ bo,
    float* __restrict__ out)
{
    __shared__ __align__(16) float sh[13120];
    unsigned sense = 0;
    const int bid = blockIdx.x;
    const int tid = threadIdx.x;
    const int gthread = bid * NT + tid;

    // INIT-A: copy state; seed EA with bea
    for (int i = gthread; i < NN * MM; i += NB * NT) g_mem[i] = mem0[i];
    for (int i = gthread; i < B_ * NN; i += NB * NT) {
        g_wr[i] = wr0[i];
        g_ww[i] = ww0[i];
    }
    for (int j = bid; j < 4; j += NB)
        seed_bcast(g_EA, bea, 2 * MM, B_ * 2 * MM, j, 4);
    gbar(sense);                                             // 1

    // INIT-B: EA(0) += h0 @ Wea   (ksplit4, K=128, 128 jobs)
    for (int j = bid; j < 128; j += NB) {
        int ks = j & 3, rest = j >> 2;
        int row0 = (rest & 1) * 128, col0 = (rest >> 1) * 64;
        tile_gemm2<false, 0, 1>(sh,
            h0 + (size_t)row0 * H_ + ks * 128, H_,
            Wea + (size_t)(ks * 128) * (2 * MM) + col0, 2 * MM, 64,
            g_EA + (size_t)row0 * (2 * MM) + col0, 2 * MM, 128);
    }
    gbar(sense);                                             // 2

    for (int t = 0; t < T_; t++) {
        // ---- P1: memupd(128) + seeds(8) = 136 ----
        for (int j = bid; j < 136; j += NB) {
            if (j < 128) {
                tile_memupd(sh, (j >> 3) * 64, (j & 7) * 64);
            } else if (j < 130) {
                seed_zero(g_r, B_ * MM, j - 128, 2);
            } else if (j < 132) {
                seed_bcast(g_hpre, bh, H_, B_ * H_, j - 130, 2);
            } else if (j < 134) {
                seed_pbias(g_Pw, bhw, j - 132, 2);
            } else {
                seed_pbias(g_Pr, bhr, j - 134, 2);
            }
        }
        gbar(sense);

        // ---- P2: r(64, K=256) + hx(32, K=256) + norms(16) + seedC(8) = 120 --
        for (int j = bid; j < 120; j += NB) {
            if (j < 64) {
                int ks = j & 3, rest = j >> 2;
                int row0 = (rest & 1) * 128, col0 = (rest >> 1) * 64;
                tile_gemm2<false, 0, 1>(sh,
                    g_wr + (size_t)row0 * NN + ks * 256, NN,
                    g_mem + (size_t)(ks * 256) * MM + col0, MM, 64,
                    g_r + (size_t)row0 * MM + col0, MM, 256);
            } else if (j < 96) {
                int jj = j - 64;
                int ks = jj & 1, rest = jj >> 1;
                int row0 = (rest & 1) * 128, col0 = (rest >> 1) * 64;
                tile_gemm2<false, 0, 1>(sh,
                    x + (size_t)row0 * (T_ * I_) + (size_t)t * I_ + ks * 256, T_ * I_,
                    Wx + (size_t)(ks * 256) * H_ + col0, H_, 64,
                    g_hpre + (size_t)row0 * H_ + col0, H_, 256);
            } else if (j < 112) {
                norm_job(j - 96);
            } else {
                int jj = j - 112;
                if (jj < 4) seed_zero(g_Cw, B_ * NN, jj, 4);
                else        seed_zero(g_Cr, B_ * NN, jj - 4, 4);
            }
        }
        gbar(sense);

        // ---- P3: hr(128, K=64 ksplit8) + seedEA(4) + seedOpre(2) = 134 ----
        for (int j = bid; j < 134; j += NB) {
            if (j < 128) {
                int ks = j & 7, rest = j >> 3;
                int row0 = (rest & 1) * 128, col0 = (rest >> 1) * 64;
                tile_gemm2<false, 0, 1>(sh,
                    g_r + (size_t)row0 * MM + ks * 64, MM,
                    Wr + (size_t)(ks * 64) * H_ + col0, H_, 64,
                    g_hpre + (size_t)row0 * H_ + col0, H_, 64);
            } else if (j < 132) {
                seed_bcast(g_EA, bea, 2 * MM, B_ * 2 * MM, j - 128, 4);
            } else {
                seed_bcast(g_opre, bo, OO, B_ * OO, j - 132, 2);
            }
        }
        gbar(sense);

        // ---- P4: Pw(36) + Pr(36) + out(32) = 104, K=256, A = tanh(hpre) ----
        for (int j = bid; j < 104; j += NB) {
            if (j < 72) {
                int head = j / 36, jj = j % 36;
                int ks = jj & 1, rest = jj >> 1;
                int row0 = (rest & 1) * 128, ct = rest >> 1;
                int col0 = ct * 64;
                int wv = PW_ - col0; if (wv > 64) wv = 64;
                const float* Wh = head ? Whr : Whw;
                float* dst = head ? g_Pr : g_Pw;
                tile_gemm2<true, 1, 1>(sh,
                    g_hpre + (size_t)row0 * H_ + ks * 256, H_,
                    Wh + (size_t)(ks * 256) * PW_ + col0, PW_, wv,
                    dst + (size_t)row0 * PSTR + col0, PSTR, 256);
            } else {
                int jj = j - 72;
                int ks = jj & 1, rest = jj >> 1;
                int row0 = (rest & 1) * 128, col0 = (rest >> 1) * 64;
                tile_gemm2<true, 0, 1>(sh,
                    g_hpre + (size_t)row0 * H_ + ks * 256, H_,
                    Wo + (size_t)(ks * 256) * OO + col0, OO, 64,
                    g_opre + (size_t)row0 * OO + col0, OO, 256);
            }
        }
        gbar(sense);

        // ---- P5: scores 128 jobs (K=256) ----
        for (int j = bid; j < 128; j += NB) {
            int z = j >> 6, jj = j & 63;
            int ks = jj & 1, rest = jj >> 1;
            int row0 = (rest & 1) * 128, n0 = (rest >> 1) * 64;
            const float* P = (z ? g_Pr : g_Pw) + (size_t)row0 * PSTR + ks * 256;
            float* Cd = (z ? g_Cr : g_Cw) + (size_t)row0 * NN + n0;
            tile_gemm2<true, 2, 1>(sh,
                P, PSTR,
                g_mem + (size_t)n0 * MM + ks * 256, MM, 64,
                Cd, NN, 256);
        }
        gbar(sense);

        // ---- P6: EA(128, K=128) + addr-dual(256) + outfin(8) = 392 ----
        for (int j = bid; j < 392; j += NB) {
            if (j < 128) {
                int ks = j & 3, rest = j >> 2;
                int row0 = (rest & 1) * 128, col0 = (rest >> 1) * 64;
                tile_gemm2<true, 0, 1>(sh,
                    g_hpre + (size_t)row0 * H_ + ks * 128, H_,
                    Wea + (size_t)(ks * 128) * (2 * MM) + col0, 2 * MM, 64,
                    g_EA + (size_t)row0 * (2 * MM) + col0, 2 * MM, 128);
            } else if (j < 384) {
                addr_dual(sh, (j - 128) * 2 + (tid >> 8));
            } else {
                int jj = j - 384;
                for (int l = tid; l < 16384; l += NT) {
                    int e = jj * 16384 + l;
                    int b = e >> 9, o = e & 511;
                    out[((size_t)b * T_ + t) * OO + o] = sigmoidf_(g_opre[e]);
                }
            }
        }
        gbar(sense);
    }
    // total barriers: 2 + 6*128 = 770 (even)
}

extern "C" void kernel_launch(void* const* d_in, const int* in_sizes, int n_in,
                              void* d_out, int out_size)
{
    (void)in_sizes; (void)n_in; (void)out_size;
    ntm_mega<<<NB, NT>>>(
        (const float*)d_in[0],  (const float*)d_in[1],  (const float*)d_in[2],
        (const float*)d_in[3],  (const float*)d_in[4],  (const float*)d_in[5],
        (const float*)d_in[6],  (const float*)d_in[7],  (const float*)d_in[8],
        (const float*)d_in[9],  (const float*)d_in[10], (const float*)d_in[11],
        (const float*)d_in[12], (const float*)d_in[13], (const float*)d_in[14],
        (const float*)d_in[15], (float*)d_out);
}